// round 11
// baseline (speedup 1.0000x reference)
#include <cuda_runtime.h>
#include <cuda_bf16.h>
#include <cstdint>

// Problem constants
#define BB   32
#define CC   128
#define NN   64
#define HID  256
#define NPX  (BB * NN * NN)        // 131072 pixels

typedef unsigned long long ULL;

// ---------- packed f32x2 helpers ----------
__device__ __forceinline__ ULL pack2(float a, float b) {
    ULL r;
    asm("mov.b64 %0, {%1, %2};" : "=l"(r) : "r"(__float_as_uint(a)), "r"(__float_as_uint(b)));
    return r;
}
__device__ __forceinline__ void unpack2(ULL v, float& a, float& b) {
    unsigned lo, hi;
    asm("mov.b64 {%0, %1}, %2;" : "=r"(lo), "=r"(hi) : "l"(v));
    a = __uint_as_float(lo); b = __uint_as_float(hi);
}
__device__ __forceinline__ ULL fma2(ULL a, ULL b, ULL c) {
    ULL d;
    asm("fma.rn.f32x2 %0, %1, %2, %3;" : "=l"(d) : "l"(a), "l"(b), "l"(c));
    return d;
}

// ---------- device scratch (no allocations allowed) ----------
__device__ float g_h1[(size_t)HID * NPX];             // 134 MB hidden activations
__device__ float g_rowpart[2 * BB * NN];              // per-half row-score partials
__device__ float g_cp[2 * 1024 * NN];                 // per-(half, pxtile) col partials
__device__ float g_rowscore[BB * NN];
__device__ float g_colscore[BB * NN];
__device__ float g_P[2 * BB * NN * NN];               // [kind][b][i][j]

// =====================================================================
// Kernel 1: conv1 + relu  ->  g_h1
// GEMM: h1[o=256, p=131072] = relu(W1[256,128] @ X[128,p] + b1)
// grid (1024 px-tiles of 128, 2 out-halves), 256 threads, 2 blocks/SM.
// thread tile: 8 outputs (4 o-pairs) x 8 px (two quads at +0 / +64).
// =====================================================================
#define CK  16            // k-chunk
#define WTP 132           // padded row (132*4 = 528 bytes, 16B-aligned rows)

__global__ void __launch_bounds__(256, 2) conv1_kernel(
    const float* __restrict__ x, const float* __restrict__ w1,
    const float* __restrict__ b1)
{
    __shared__ float xs[CK][128];
    __shared__ float wts[CK][WTP];

    const int tid  = threadIdx.x;
    const int t    = blockIdx.x;       // px tile (128 px)
    const int half = blockIdx.y;
    const int og   = tid >> 4;         // 0..15 (8 outputs each)
    const int pg   = tid & 15;         // 0..15 (8 px each: pg*4 and 64+pg*4)
    const int obase = half * 128 + og * 8;

    const int bidx   = (t * 128) >> 12;
    const int binner = (t * 128) & 4095;
    const float* xb = x + ((size_t)bidx * CC) * 4096 + binner;

    // staging index precompute
    const int f0 = tid, f1 = tid + 256;
    const int xc0 = f0 >> 5, xp0 = f0 & 31;    // xs: 512 float4, 2/thread
    const int xc1 = f1 >> 5, xp1 = f1 & 31;
    const int wo0 = f0 >> 2, wc0 = f0 & 3;     // wts: 512 float4, 2/thread
    const int wo1 = f1 >> 2, wc1 = f1 & 3;

    // accumulators: acc[o-pair][px], init with bias
    ULL acc[4][8];
    #pragma unroll
    for (int op = 0; op < 4; op++) {
        ULL p = pack2(__ldg(&b1[obase + op * 2]), __ldg(&b1[obase + op * 2 + 1]));
        #pragma unroll
        for (int q = 0; q < 8; q++) acc[op][q] = p;
    }

    // preload chunk 0
    float4 xr0 = *reinterpret_cast<const float4*>(&xb[(size_t)xc0 * 4096 + xp0 * 4]);
    float4 xr1 = *reinterpret_cast<const float4*>(&xb[(size_t)xc1 * 4096 + xp1 * 4]);
    float4 wr0 = *reinterpret_cast<const float4*>(&w1[(half * 128 + wo0) * CC + wc0 * 4]);
    float4 wr1 = *reinterpret_cast<const float4*>(&w1[(half * 128 + wo1) * CC + wc1 * 4]);

    for (int kc = 0; kc < CC / CK; kc++) {
        __syncthreads();
        *reinterpret_cast<float4*>(&xs[xc0][xp0 * 4]) = xr0;
        *reinterpret_cast<float4*>(&xs[xc1][xp1 * 4]) = xr1;
        wts[wc0 * 4 + 0][wo0] = wr0.x; wts[wc0 * 4 + 1][wo0] = wr0.y;
        wts[wc0 * 4 + 2][wo0] = wr0.z; wts[wc0 * 4 + 3][wo0] = wr0.w;
        wts[wc1 * 4 + 0][wo1] = wr1.x; wts[wc1 * 4 + 1][wo1] = wr1.y;
        wts[wc1 * 4 + 2][wo1] = wr1.z; wts[wc1 * 4 + 3][wo1] = wr1.w;
        __syncthreads();

        if (kc + 1 < CC / CK) {
            int k = (kc + 1) * CK;
            xr0 = *reinterpret_cast<const float4*>(&xb[(size_t)(k + xc0) * 4096 + xp0 * 4]);
            xr1 = *reinterpret_cast<const float4*>(&xb[(size_t)(k + xc1) * 4096 + xp1 * 4]);
            wr0 = *reinterpret_cast<const float4*>(&w1[(half * 128 + wo0) * CC + k + wc0 * 4]);
            wr1 = *reinterpret_cast<const float4*>(&w1[(half * 128 + wo1) * CC + k + wc1 * 4]);
        }

        #pragma unroll
        for (int c = 0; c < CK; c++) {
            ulonglong2 wa = *reinterpret_cast<const ulonglong2*>(&wts[c][og * 8]);
            ulonglong2 wb = *reinterpret_cast<const ulonglong2*>(&wts[c][og * 8 + 4]);
            float4 xa = *reinterpret_cast<const float4*>(&xs[c][pg * 4]);
            float4 xc = *reinterpret_cast<const float4*>(&xs[c][64 + pg * 4]);
            ULL xp[8];
            xp[0] = pack2(xa.x, xa.x); xp[1] = pack2(xa.y, xa.y);
            xp[2] = pack2(xa.z, xa.z); xp[3] = pack2(xa.w, xa.w);
            xp[4] = pack2(xc.x, xc.x); xp[5] = pack2(xc.y, xc.y);
            xp[6] = pack2(xc.z, xc.z); xp[7] = pack2(xc.w, xc.w);
            #pragma unroll
            for (int q = 0; q < 8; q++) {
                acc[0][q] = fma2(wa.x, xp[q], acc[0][q]);
                acc[1][q] = fma2(wa.y, xp[q], acc[1][q]);
                acc[2][q] = fma2(wb.x, xp[q], acc[2][q]);
                acc[3][q] = fma2(wb.y, xp[q], acc[3][q]);
            }
        }
    }

    // relu + store h1
    const size_t pxb = (size_t)t * 128 + pg * 4;
    #pragma unroll
    for (int op = 0; op < 4; op++) {
        int o = obase + op * 2;
        float a0, b0, a1, b1v, a2, b2v, a3, b3;
        unpack2(acc[op][0], a0, b0); unpack2(acc[op][1], a1, b1v);
        unpack2(acc[op][2], a2, b2v); unpack2(acc[op][3], a3, b3);
        float4 lo = make_float4(fmaxf(a0,0.f), fmaxf(a1,0.f), fmaxf(a2,0.f), fmaxf(a3,0.f));
        float4 hi = make_float4(fmaxf(b0,0.f), fmaxf(b1v,0.f), fmaxf(b2v,0.f), fmaxf(b3,0.f));
        *reinterpret_cast<float4*>(&g_h1[(size_t)o * NPX + pxb])       = lo;
        *reinterpret_cast<float4*>(&g_h1[(size_t)(o + 1) * NPX + pxb]) = hi;
        unpack2(acc[op][4], a0, b0); unpack2(acc[op][5], a1, b1v);
        unpack2(acc[op][6], a2, b2v); unpack2(acc[op][7], a3, b3);
        float4 lo2 = make_float4(fmaxf(a0,0.f), fmaxf(a1,0.f), fmaxf(a2,0.f), fmaxf(a3,0.f));
        float4 hi2 = make_float4(fmaxf(b0,0.f), fmaxf(b1v,0.f), fmaxf(b2v,0.f), fmaxf(b3,0.f));
        *reinterpret_cast<float4*>(&g_h1[(size_t)o * NPX + pxb + 64])       = lo2;
        *reinterpret_cast<float4*>(&g_h1[(size_t)(o + 1) * NPX + pxb + 64]) = hi2;
    }
}

// =====================================================================
// Kernel 2: conv2 + relu + score partials (h2 never hits memory).
// Same tiling; k = 256 (16 chunks). Epilogue computes row/col partials.
// =====================================================================
__global__ void __launch_bounds__(256, 2) conv2_kernel(
    const float* __restrict__ w2, const float* __restrict__ b2,
    const float* __restrict__ w_row, const float* __restrict__ w_col)
{
    __shared__ float xs[CK][128];
    __shared__ float wts[CK][WTP];
    __shared__ float redr[2][8];
    __shared__ float colred[64];

    const int tid  = threadIdx.x;
    const int t    = blockIdx.x;
    const int half = blockIdx.y;
    const int og   = tid >> 4;
    const int pg   = tid & 15;
    const int obase = half * 128 + og * 8;

    if (tid < 64) colred[tid] = 0.f;

    const float* xb = g_h1 + (size_t)t * 128;   // + c*NPX + lp

    const int f0 = tid, f1 = tid + 256;
    const int xc0 = f0 >> 5, xp0 = f0 & 31;
    const int xc1 = f1 >> 5, xp1 = f1 & 31;
    const int wo0 = f0 >> 2, wc0 = f0 & 3;
    const int wo1 = f1 >> 2, wc1 = f1 & 3;

    ULL acc[4][8];
    #pragma unroll
    for (int op = 0; op < 4; op++) {
        ULL p = pack2(__ldg(&b2[obase + op * 2]), __ldg(&b2[obase + op * 2 + 1]));
        #pragma unroll
        for (int q = 0; q < 8; q++) acc[op][q] = p;
    }

    float4 xr0 = *reinterpret_cast<const float4*>(&xb[(size_t)xc0 * NPX + xp0 * 4]);
    float4 xr1 = *reinterpret_cast<const float4*>(&xb[(size_t)xc1 * NPX + xp1 * 4]);
    float4 wr0 = *reinterpret_cast<const float4*>(&w2[(half * 128 + wo0) * HID + wc0 * 4]);
    float4 wr1 = *reinterpret_cast<const float4*>(&w2[(half * 128 + wo1) * HID + wc1 * 4]);

    for (int kc = 0; kc < HID / CK; kc++) {
        __syncthreads();
        *reinterpret_cast<float4*>(&xs[xc0][xp0 * 4]) = xr0;
        *reinterpret_cast<float4*>(&xs[xc1][xp1 * 4]) = xr1;
        wts[wc0 * 4 + 0][wo0] = wr0.x; wts[wc0 * 4 + 1][wo0] = wr0.y;
        wts[wc0 * 4 + 2][wo0] = wr0.z; wts[wc0 * 4 + 3][wo0] = wr0.w;
        wts[wc1 * 4 + 0][wo1] = wr1.x; wts[wc1 * 4 + 1][wo1] = wr1.y;
        wts[wc1 * 4 + 2][wo1] = wr1.z; wts[wc1 * 4 + 3][wo1] = wr1.w;
        __syncthreads();

        if (kc + 1 < HID / CK) {
            int k = (kc + 1) * CK;
            xr0 = *reinterpret_cast<const float4*>(&xb[(size_t)(k + xc0) * NPX + xp0 * 4]);
            xr1 = *reinterpret_cast<const float4*>(&xb[(size_t)(k + xc1) * NPX + xp1 * 4]);
            wr0 = *reinterpret_cast<const float4*>(&w2[(half * 128 + wo0) * HID + k + wc0 * 4]);
            wr1 = *reinterpret_cast<const float4*>(&w2[(half * 128 + wo1) * HID + k + wc1 * 4]);
        }

        #pragma unroll
        for (int c = 0; c < CK; c++) {
            ulonglong2 wa = *reinterpret_cast<const ulonglong2*>(&wts[c][og * 8]);
            ulonglong2 wb = *reinterpret_cast<const ulonglong2*>(&wts[c][og * 8 + 4]);
            float4 xa = *reinterpret_cast<const float4*>(&xs[c][pg * 4]);
            float4 xc = *reinterpret_cast<const float4*>(&xs[c][64 + pg * 4]);
            ULL xp[8];
            xp[0] = pack2(xa.x, xa.x); xp[1] = pack2(xa.y, xa.y);
            xp[2] = pack2(xa.z, xa.z); xp[3] = pack2(xa.w, xa.w);
            xp[4] = pack2(xc.x, xc.x); xp[5] = pack2(xc.y, xc.y);
            xp[6] = pack2(xc.z, xc.z); xp[7] = pack2(xc.w, xc.w);
            #pragma unroll
            for (int q = 0; q < 8; q++) {
                acc[0][q] = fma2(wa.x, xp[q], acc[0][q]);
                acc[1][q] = fma2(wa.y, xp[q], acc[1][q]);
                acc[2][q] = fma2(wb.x, xp[q], acc[2][q]);
                acc[3][q] = fma2(wb.y, xp[q], acc[3][q]);
            }
        }
    }

    // ---- epilogue: relu + score partials (h2 stays in registers) ----
    const int bh0 = t * 2;               // quad0 row; quad1 is bh0+1 (same b)
    const int h0 = bh0 & 63;
    float rp0 = 0.f, rp1 = 0.f;
    float cp[4] = {0.f, 0.f, 0.f, 0.f};

    #pragma unroll
    for (int op = 0; op < 4; op++) {
        int o = obase + op * 2;
        float a[8][2];
        #pragma unroll
        for (int q = 0; q < 8; q++) {
            unpack2(acc[op][q], a[q][0], a[q][1]);
            a[q][0] = fmaxf(a[q][0], 0.f);
            a[q][1] = fmaxf(a[q][1], 0.f);
        }
        float4 wrA = __ldg(reinterpret_cast<const float4*>(&w_row[o * NN + pg * 4]));
        float4 wrB = __ldg(reinterpret_cast<const float4*>(&w_row[(o + 1) * NN + pg * 4]));
        rp0 += a[0][0]*wrA.x + a[1][0]*wrA.y + a[2][0]*wrA.z + a[3][0]*wrA.w
             + a[0][1]*wrB.x + a[1][1]*wrB.y + a[2][1]*wrB.z + a[3][1]*wrB.w;
        rp1 += a[4][0]*wrA.x + a[5][0]*wrA.y + a[6][0]*wrA.z + a[7][0]*wrA.w
             + a[4][1]*wrB.x + a[5][1]*wrB.y + a[6][1]*wrB.z + a[7][1]*wrB.w;
        float wc00 = __ldg(&w_col[o * NN + h0]);
        float wc01 = __ldg(&w_col[(o + 1) * NN + h0]);
        float wc10 = __ldg(&w_col[o * NN + h0 + 1]);
        float wc11 = __ldg(&w_col[(o + 1) * NN + h0 + 1]);
        #pragma unroll
        for (int q = 0; q < 4; q++) {
            cp[q] += a[q][0] * wc00 + a[q][1] * wc01
                   + a[4+q][0] * wc10 + a[4+q][1] * wc11;
        }
    }

    // row partials: full warp reduce, then per-warp slots
    #pragma unroll
    for (int m = 16; m >= 1; m >>= 1) {
        rp0 += __shfl_xor_sync(0xffffffffu, rp0, m);
        rp1 += __shfl_xor_sync(0xffffffffu, rp1, m);
    }
    if ((tid & 31) == 0) { redr[0][tid >> 5] = rp0; redr[1][tid >> 5] = rp1; }

    // col partials: fold og pairs, then smem atomic across warps
    #pragma unroll
    for (int q = 0; q < 4; q++)
        cp[q] += __shfl_xor_sync(0xffffffffu, cp[q], 16);
    if ((tid & 31) < 16) {
        #pragma unroll
        for (int q = 0; q < 4; q++) atomicAdd(&colred[pg * 4 + q], cp[q]);
    }
    __syncthreads();

    if (tid < 2) {
        float s = 0.f;
        #pragma unroll
        for (int w = 0; w < 8; w++) s += redr[tid][w];
        g_rowpart[half * (BB * NN) + bh0 + tid] = s;
    }
    if (tid < 64)
        g_cp[((size_t)half * 1024 + t) * NN + tid] = colred[tid];
}

// =====================================================================
// Kernel 3: combine partials into final scores
// =====================================================================
__global__ void combine_kernel(const float* __restrict__ b_row,
                               const float* __restrict__ b_col)
{
    int b = blockIdx.x;       // 0..31
    int w = threadIdx.x;      // 0..63
    float s = __ldg(&b_col[0]);
    #pragma unroll 4
    for (int tt = 0; tt < 32; tt++) {
        s += g_cp[(size_t)(b * 32 + tt) * NN + w];
        s += g_cp[(size_t)(1024 + b * 32 + tt) * NN + w];
    }
    g_colscore[b * NN + w] = s;
    int bh = b * NN + w;
    g_rowscore[bh] = g_rowpart[bh] + g_rowpart[BB * NN + bh] + __ldg(&b_row[0]);
}

// =====================================================================
// Kernel 4: differentiable bitonic sort -> permutation matrix P
// =====================================================================
#define PPAD 65
__global__ void __launch_bounds__(256) sort_kernel()
{
    __shared__ float P[NN * PPAD];
    __shared__ float xsh[NN];
    __shared__ float alph[32];
    __shared__ int   pa[32], pb[32];

    const int tid  = threadIdx.x;
    const int s    = blockIdx.x;
    const int kind = s >> 5;
    const int b    = s & 31;
    const float* sc = kind ? g_colscore : g_rowscore;

    if (tid < NN) xsh[tid] = sc[b * NN + tid];
    for (int idx = tid; idx < NN * NN; idx += 256) {
        int r = idx >> 6, c = idx & 63;
        P[r * PPAD + c] = (r == c) ? 1.f : 0.f;
    }
    __syncthreads();

    for (int blk = 0; blk < 6; blk++) {
        for (int lay = 0; lay <= blk; lay++) {
            int m = 1 << (blk - lay);
            if (tid < 32) {
                int q  = tid;
                int ix = ((q & ~(m - 1)) << 1) | (q & (m - 1));
                int a = ix, bidx = ix + m;
                if ((ix >> (blk + 1)) & 1) { int tswap = a; a = bidx; bidx = tswap; }
                pa[q] = a; pb[q] = bidx;
                float xa = xsh[a], xb = xsh[bidx];
                float al = atanf((xb - xa) * 50.f) * 0.31830988618379067f + 0.5f;
                alph[q] = al;
                xsh[a]    = al * xa + (1.f - al) * xb;
                xsh[bidx] = (1.f - al) * xa + al * xb;
            }
            __syncthreads();
            #pragma unroll
            for (int it = 0; it < 8; it++) {
                int idx = tid + it * 256;
                int r = idx >> 5, q = idx & 31;
                int a = pa[q], bidx = pb[q];
                float al = alph[q];
                float Pa = P[r * PPAD + a], Pb = P[r * PPAD + bidx];
                P[r * PPAD + a]    = al * Pa + (1.f - al) * Pb;
                P[r * PPAD + bidx] = (1.f - al) * Pa + al * Pb;
            }
            __syncthreads();
        }
    }

    for (int idx = tid; idx < NN * NN; idx += 256)
        g_P[(size_t)(kind * BB + b) * NN * NN + idx] = P[(idx >> 6) * PPAD + (idx & 63)];
}

// =====================================================================
// Kernel 5: out[b,c] = P_col * (P_row * X)^T     (one block per (b,c))
// =====================================================================
#define YPAD 68
struct ApplySmem {
    float Xs[NN * NN];
    float Prs[NN * PPAD];
    float Pcs[NN * PPAD];
    float Yt[NN * YPAD];
};

__global__ void __launch_bounds__(128) apply_kernel(
    const float* __restrict__ x, float* __restrict__ out)
{
    extern __shared__ unsigned char dyn_smem[];
    ApplySmem* sm = reinterpret_cast<ApplySmem*>(dyn_smem);

    const int tid = threadIdx.x;
    const int bc  = blockIdx.x;
    const int b   = bc >> 7;

    {
        const float4* xg = reinterpret_cast<const float4*>(x) + (size_t)bc * (NN * NN / 4);
        float4* Xs4 = reinterpret_cast<float4*>(sm->Xs);
        #pragma unroll
        for (int j = 0; j < 8; j++) Xs4[tid + j * 128] = xg[tid + j * 128];
    }
    {
        const float4* pr4 = reinterpret_cast<const float4*>(&g_P[(size_t)b * NN * NN]);
        const float4* pc4 = reinterpret_cast<const float4*>(&g_P[(size_t)(BB + b) * NN * NN]);
        #pragma unroll
        for (int j = 0; j < 8; j++) {
            int idx = tid + j * 128;
            int l = idx * 4, r = l >> 6, c = l & 63;
            float4 v = pr4[idx];
            float* d = &sm->Prs[r * PPAD + c];
            d[0] = v.x; d[1] = v.y; d[2] = v.z; d[3] = v.w;
            float4 u = pc4[idx];
            float* e = &sm->Pcs[r * PPAD + c];
            e[0] = u.x; e[1] = u.y; e[2] = u.z; e[3] = u.w;
        }
    }
    __syncthreads();

    const int ig = tid >> 4, kg = tid & 15;
    const int i0 = ig * 8,   k0 = kg * 4;

    ULL acc[8][2];
    #pragma unroll
    for (int ii = 0; ii < 8; ii++) { acc[ii][0] = 0ull; acc[ii][1] = 0ull; }

    #pragma unroll 4
    for (int j = 0; j < NN; j++) {
        const ULL* xp = reinterpret_cast<const ULL*>(&sm->Xs[j * NN + k0]);
        ULL xv0 = xp[0], xv1 = xp[1];
        #pragma unroll
        for (int ii = 0; ii < 8; ii++) {
            float p = sm->Prs[(i0 + ii) * PPAD + j];
            ULL pp = pack2(p, p);
            acc[ii][0] = fma2(xv0, pp, acc[ii][0]);
            acc[ii][1] = fma2(xv1, pp, acc[ii][1]);
        }
    }
    {
        float yv[8][4];
        #pragma unroll
        for (int ii = 0; ii < 8; ii++) {
            unpack2(acc[ii][0], yv[ii][0], yv[ii][1]);
            unpack2(acc[ii][1], yv[ii][2], yv[ii][3]);
        }
        #pragma unroll
        for (int kk = 0; kk < 4; kk++) {
            float4 v0 = make_float4(yv[0][kk], yv[1][kk], yv[2][kk], yv[3][kk]);
            float4 v1 = make_float4(yv[4][kk], yv[5][kk], yv[6][kk], yv[7][kk]);
            *reinterpret_cast<float4*>(&sm->Yt[(k0 + kk) * YPAD + i0])     = v0;
            *reinterpret_cast<float4*>(&sm->Yt[(k0 + kk) * YPAD + i0 + 4]) = v1;
        }
    }
    __syncthreads();

    #pragma unroll
    for (int ii = 0; ii < 8; ii++) { acc[ii][0] = 0ull; acc[ii][1] = 0ull; }

    #pragma unroll 4
    for (int j = 0; j < NN; j++) {
        const ULL* yp = reinterpret_cast<const ULL*>(&sm->Yt[j * YPAD + k0]);
        ULL yv0 = yp[0], yv1 = yp[1];
        #pragma unroll
        for (int ii = 0; ii < 8; ii++) {
            float p = sm->Pcs[(i0 + ii) * PPAD + j];
            ULL pp = pack2(p, p);
            acc[ii][0] = fma2(yv0, pp, acc[ii][0]);
            acc[ii][1] = fma2(yv1, pp, acc[ii][1]);
        }
    }

    float* og = out + (size_t)bc * NN * NN;
    #pragma unroll
    for (int ii = 0; ii < 8; ii++) {
        float o0, o1, o2, o3;
        unpack2(acc[ii][0], o0, o1);
        unpack2(acc[ii][1], o2, o3);
        *reinterpret_cast<float4*>(&og[(ii + i0) * NN + k0]) = make_float4(o0, o1, o2, o3);
    }
}

// =====================================================================
// launcher
// =====================================================================
extern "C" void kernel_launch(void* const* d_in, const int* in_sizes, int n_in,
                              void* d_out, int out_size)
{
    const float* x     = (const float*)d_in[0];
    const float* w1    = (const float*)d_in[1];
    const float* b1    = (const float*)d_in[2];
    const float* w2    = (const float*)d_in[3];
    const float* b2    = (const float*)d_in[4];
    const float* w_row = (const float*)d_in[5];
    const float* b_row = (const float*)d_in[6];
    const float* w_col = (const float*)d_in[7];
    const float* b_col = (const float*)d_in[8];
    float* out = (float*)d_out;

    const int apply_smem = (int)sizeof(ApplySmem);
    cudaFuncSetAttribute(apply_kernel, cudaFuncAttributeMaxDynamicSharedMemorySize, apply_smem);

    conv1_kernel<<<dim3(1024, 2), 256>>>(x, w1, b1);
    conv2_kernel<<<dim3(1024, 2), 256>>>(w2, b2, w_row, w_col);
    combine_kernel<<<BB, NN>>>(b_row, b_col);
    sort_kernel<<<2 * BB, 256>>>();
    apply_kernel<<<BB * CC, 128, apply_smem>>>(x, out);
}

// round 12
// speedup vs baseline: 1.0944x; 1.0944x over previous
#include <cuda_runtime.h>
#include <cuda_bf16.h>
#include <cstdint>

// Problem constants
#define BB   32
#define CC   128
#define NN   64
#define HID  256
#define NPX  (BB * NN * NN)        // 131072 pixels

typedef unsigned long long ULL;
typedef unsigned int uint;

// ---------- packed f32x2 helpers ----------
__device__ __forceinline__ ULL pack2(float a, float b) {
    ULL r;
    asm("mov.b64 %0, {%1, %2};" : "=l"(r) : "r"(__float_as_uint(a)), "r"(__float_as_uint(b)));
    return r;
}
__device__ __forceinline__ void unpack2(ULL v, float& a, float& b) {
    unsigned lo, hi;
    asm("mov.b64 {%0, %1}, %2;" : "=r"(lo), "=r"(hi) : "l"(v));
    a = __uint_as_float(lo); b = __uint_as_float(hi);
}
__device__ __forceinline__ ULL fma2(ULL a, ULL b, ULL c) {
    ULL d;
    asm("fma.rn.f32x2 %0, %1, %2, %3;" : "=l"(d) : "l"(a), "l"(b), "l"(c));
    return d;
}

// ---------- mma.sync m16n8k16 bf16 ----------
#define MMA16816(d, a, b) \
    asm volatile("mma.sync.aligned.m16n8k16.row.col.f32.bf16.bf16.f32 " \
                 "{%0,%1,%2,%3}, {%4,%5,%6,%7}, {%8,%9}, {%0,%1,%2,%3};" \
                 : "+f"((d)[0]), "+f"((d)[1]), "+f"((d)[2]), "+f"((d)[3]) \
                 : "r"((a)[0]), "r"((a)[1]), "r"((a)[2]), "r"((a)[3]), \
                   "r"((b)[0]), "r"((b)[1]))

// ---------- device scratch (no allocations allowed) ----------
__device__ __nv_bfloat16 g_hhi[(size_t)NPX * HID];    // 67 MB  h1 hi split, [px][k]
__device__ __nv_bfloat16 g_hlo[(size_t)NPX * HID];    // 67 MB  h1 lo split
__device__ __nv_bfloat16 g_w2hi[HID * HID];
__device__ __nv_bfloat16 g_w2lo[HID * HID];
__device__ float g_rowpart[2 * BB * NN];
__device__ float g_cp[2 * 1024 * NN];
__device__ float g_rowscore[BB * NN];
__device__ float g_colscore[BB * NN];
__device__ float g_P[2 * BB * NN * NN];

// =====================================================================
// Kernel 0: split w2 into bf16 hi/lo
// =====================================================================
__global__ void prep_w2_kernel(const float* __restrict__ w2)
{
    int i = blockIdx.x * 256 + threadIdx.x;
    if (i < HID * HID) {
        float f = w2[i];
        __nv_bfloat16 h = __float2bfloat16(f);
        g_w2hi[i] = h;
        g_w2lo[i] = __float2bfloat16(f - __bfloat162float(h));
    }
}

// =====================================================================
// Kernel 1: conv1 + relu -> split bf16 h1 in [px][k] layout.
// fp32x2 GEMM (round-11 proven structure), epilogue changed.
// =====================================================================
#define CK  16
#define WTP 132

__global__ void __launch_bounds__(256, 2) conv1_kernel(
    const float* __restrict__ x, const float* __restrict__ w1,
    const float* __restrict__ b1)
{
    __shared__ float xs[CK][128];
    __shared__ float wts[CK][WTP];

    const int tid  = threadIdx.x;
    const int t    = blockIdx.x;
    const int half = blockIdx.y;
    const int og   = tid >> 4;
    const int pg   = tid & 15;
    const int obase = half * 128 + og * 8;

    const int bidx   = (t * 128) >> 12;
    const int binner = (t * 128) & 4095;
    const float* xb = x + ((size_t)bidx * CC) * 4096 + binner;

    const int f0 = tid, f1 = tid + 256;
    const int xc0 = f0 >> 5, xp0 = f0 & 31;
    const int xc1 = f1 >> 5, xp1 = f1 & 31;
    const int wo0 = f0 >> 2, wc0 = f0 & 3;
    const int wo1 = f1 >> 2, wc1 = f1 & 3;

    ULL acc[4][8];
    #pragma unroll
    for (int op = 0; op < 4; op++) {
        ULL p = pack2(__ldg(&b1[obase + op * 2]), __ldg(&b1[obase + op * 2 + 1]));
        #pragma unroll
        for (int q = 0; q < 8; q++) acc[op][q] = p;
    }

    float4 xr0 = *reinterpret_cast<const float4*>(&xb[(size_t)xc0 * 4096 + xp0 * 4]);
    float4 xr1 = *reinterpret_cast<const float4*>(&xb[(size_t)xc1 * 4096 + xp1 * 4]);
    float4 wr0 = *reinterpret_cast<const float4*>(&w1[(half * 128 + wo0) * CC + wc0 * 4]);
    float4 wr1 = *reinterpret_cast<const float4*>(&w1[(half * 128 + wo1) * CC + wc1 * 4]);

    for (int kc = 0; kc < CC / CK; kc++) {
        __syncthreads();
        *reinterpret_cast<float4*>(&xs[xc0][xp0 * 4]) = xr0;
        *reinterpret_cast<float4*>(&xs[xc1][xp1 * 4]) = xr1;
        wts[wc0 * 4 + 0][wo0] = wr0.x; wts[wc0 * 4 + 1][wo0] = wr0.y;
        wts[wc0 * 4 + 2][wo0] = wr0.z; wts[wc0 * 4 + 3][wo0] = wr0.w;
        wts[wc1 * 4 + 0][wo1] = wr1.x; wts[wc1 * 4 + 1][wo1] = wr1.y;
        wts[wc1 * 4 + 2][wo1] = wr1.z; wts[wc1 * 4 + 3][wo1] = wr1.w;
        __syncthreads();

        if (kc + 1 < CC / CK) {
            int k = (kc + 1) * CK;
            xr0 = *reinterpret_cast<const float4*>(&xb[(size_t)(k + xc0) * 4096 + xp0 * 4]);
            xr1 = *reinterpret_cast<const float4*>(&xb[(size_t)(k + xc1) * 4096 + xp1 * 4]);
            wr0 = *reinterpret_cast<const float4*>(&w1[(half * 128 + wo0) * CC + k + wc0 * 4]);
            wr1 = *reinterpret_cast<const float4*>(&w1[(half * 128 + wo1) * CC + k + wc1 * 4]);
        }

        #pragma unroll
        for (int c = 0; c < CK; c++) {
            ulonglong2 wa = *reinterpret_cast<const ulonglong2*>(&wts[c][og * 8]);
            ulonglong2 wb = *reinterpret_cast<const ulonglong2*>(&wts[c][og * 8 + 4]);
            float4 xa = *reinterpret_cast<const float4*>(&xs[c][pg * 4]);
            float4 xc = *reinterpret_cast<const float4*>(&xs[c][64 + pg * 4]);
            ULL xp[8];
            xp[0] = pack2(xa.x, xa.x); xp[1] = pack2(xa.y, xa.y);
            xp[2] = pack2(xa.z, xa.z); xp[3] = pack2(xa.w, xa.w);
            xp[4] = pack2(xc.x, xc.x); xp[5] = pack2(xc.y, xc.y);
            xp[6] = pack2(xc.z, xc.z); xp[7] = pack2(xc.w, xc.w);
            #pragma unroll
            for (int q = 0; q < 8; q++) {
                acc[0][q] = fma2(wa.x, xp[q], acc[0][q]);
                acc[1][q] = fma2(wa.y, xp[q], acc[1][q]);
                acc[2][q] = fma2(wb.x, xp[q], acc[2][q]);
                acc[3][q] = fma2(wb.y, xp[q], acc[3][q]);
            }
        }
    }

    // ---- epilogue: relu, split into bf16 hi/lo, store [px][k] ----
    float vals[8][8];     // [q(px)][oi]
    #pragma unroll
    for (int op = 0; op < 4; op++) {
        #pragma unroll
        for (int q = 0; q < 8; q++) {
            float a, b;
            unpack2(acc[op][q], a, b);
            vals[q][op * 2]     = fmaxf(a, 0.f);
            vals[q][op * 2 + 1] = fmaxf(b, 0.f);
        }
    }
    #pragma unroll
    for (int q = 0; q < 8; q++) {
        size_t px = (size_t)t * 128 + pg * 4 + (q & 3) + (q >> 2) * 64;
        uint hi[4], lo[4];
        #pragma unroll
        for (int j = 0; j < 4; j++) {
            float f0v = vals[q][j * 2], f1v = vals[q][j * 2 + 1];
            __nv_bfloat16 h0 = __float2bfloat16(f0v);
            __nv_bfloat16 h1 = __float2bfloat16(f1v);
            __nv_bfloat162 hp; hp.x = h0; hp.y = h1;
            hi[j] = *reinterpret_cast<uint*>(&hp);
            __nv_bfloat162 lp;
            lp.x = __float2bfloat16(f0v - __bfloat162float(h0));
            lp.y = __float2bfloat16(f1v - __bfloat162float(h1));
            lo[j] = *reinterpret_cast<uint*>(&lp);
        }
        *reinterpret_cast<uint4*>(&g_hhi[px * HID + obase]) = make_uint4(hi[0], hi[1], hi[2], hi[3]);
        *reinterpret_cast<uint4*>(&g_hlo[px * HID + obase]) = make_uint4(lo[0], lo[1], lo[2], lo[3]);
    }
}

// =====================================================================
// Kernel 2: conv2 via mma.sync bf16 x3 splits + relu + score partials.
// Block: 256 thr (8 warps), tile 128 o x 128 px, K=256 in 8 chunks of 32.
// Warp: wo = warp>>2 (o 64), wp = warp&3 (px 32): 4x4 m16n8k16 tiles.
// =====================================================================
#define KC2  32
#define KCP  34     // bf16 elements per row (68B stride, 4B-aligned, ~2-way LDS)

__global__ void __launch_bounds__(256, 2) conv2_mma_kernel(
    const float* __restrict__ b2,
    const float* __restrict__ w_row, const float* __restrict__ w_col)
{
    __shared__ __nv_bfloat16 hs_hi[128][KCP];
    __shared__ __nv_bfloat16 hs_lo[128][KCP];
    __shared__ __nv_bfloat16 ws_hi[128][KCP];
    __shared__ __nv_bfloat16 ws_lo[128][KCP];
    __shared__ float colred[64];
    __shared__ float rowred[2];

    const int tid  = threadIdx.x;
    const int t    = blockIdx.x;
    const int half = blockIdx.y;
    const int warp = tid >> 5;
    const int lane = tid & 31;
    const int g    = lane >> 2;
    const int tig  = lane & 3;
    const int wo   = warp >> 2;      // 0..1
    const int wp   = warp & 3;       // 0..3

    if (tid < 64) colred[tid] = 0.f;
    if (tid < 2)  rowred[tid] = 0.f;

    const size_t pxbase = (size_t)t * 128;

    float acc[4][4][4];
    #pragma unroll
    for (int mt = 0; mt < 4; mt++)
        #pragma unroll
        for (int nt = 0; nt < 4; nt++)
            #pragma unroll
            for (int i = 0; i < 4; i++) acc[mt][nt][i] = 0.f;

    const int srow = tid >> 1;
    const int sseg = tid & 1;

    for (int kc = 0; kc < HID / KC2; kc++) {
        const int k0 = kc * KC2 + sseg * 16;
        __syncthreads();
        {
            const size_t hoff = (pxbase + srow) * HID + k0;
            const size_t woff = (size_t)(half * 128 + srow) * HID + k0;
            uint4 a0 = *reinterpret_cast<const uint4*>(&g_hhi[hoff]);
            uint4 a1 = *reinterpret_cast<const uint4*>(&g_hhi[hoff + 8]);
            uint4 b0v = *reinterpret_cast<const uint4*>(&g_hlo[hoff]);
            uint4 b1v = *reinterpret_cast<const uint4*>(&g_hlo[hoff + 8]);
            uint4 c0 = *reinterpret_cast<const uint4*>(&g_w2hi[woff]);
            uint4 c1 = *reinterpret_cast<const uint4*>(&g_w2hi[woff + 8]);
            uint4 d0 = *reinterpret_cast<const uint4*>(&g_w2lo[woff]);
            uint4 d1 = *reinterpret_cast<const uint4*>(&g_w2lo[woff + 8]);
            uint* p;
            p = reinterpret_cast<uint*>(&hs_hi[srow][sseg * 16]);
            p[0]=a0.x; p[1]=a0.y; p[2]=a0.z; p[3]=a0.w; p[4]=a1.x; p[5]=a1.y; p[6]=a1.z; p[7]=a1.w;
            p = reinterpret_cast<uint*>(&hs_lo[srow][sseg * 16]);
            p[0]=b0v.x; p[1]=b0v.y; p[2]=b0v.z; p[3]=b0v.w; p[4]=b1v.x; p[5]=b1v.y; p[6]=b1v.z; p[7]=b1v.w;
            p = reinterpret_cast<uint*>(&ws_hi[srow][sseg * 16]);
            p[0]=c0.x; p[1]=c0.y; p[2]=c0.z; p[3]=c0.w; p[4]=c1.x; p[5]=c1.y; p[6]=c1.z; p[7]=c1.w;
            p = reinterpret_cast<uint*>(&ws_lo[srow][sseg * 16]);
            p[0]=d0.x; p[1]=d0.y; p[2]=d0.z; p[3]=d0.w; p[4]=d1.x; p[5]=d1.y; p[6]=d1.z; p[7]=d1.w;
        }
        __syncthreads();

        #pragma unroll
        for (int kk = 0; kk < 2; kk++) {
            const int kb = kk * 16;
            uint a[4][4], bh[4][2], bl[4][2];
            // B fragments (hi and lo)
            #pragma unroll
            for (int nt = 0; nt < 4; nt++) {
                int rp = wp * 32 + nt * 8 + g;
                bh[nt][0] = *reinterpret_cast<const uint*>(&hs_hi[rp][kb + 2 * tig]);
                bh[nt][1] = *reinterpret_cast<const uint*>(&hs_hi[rp][kb + 2 * tig + 8]);
                bl[nt][0] = *reinterpret_cast<const uint*>(&hs_lo[rp][kb + 2 * tig]);
                bl[nt][1] = *reinterpret_cast<const uint*>(&hs_lo[rp][kb + 2 * tig + 8]);
            }
            // A = w_hi : hi*hi and hi*lo
            #pragma unroll
            for (int mt = 0; mt < 4; mt++) {
                int ro = wo * 64 + mt * 16 + g;
                a[mt][0] = *reinterpret_cast<const uint*>(&ws_hi[ro][kb + 2 * tig]);
                a[mt][1] = *reinterpret_cast<const uint*>(&ws_hi[ro + 8][kb + 2 * tig]);
                a[mt][2] = *reinterpret_cast<const uint*>(&ws_hi[ro][kb + 2 * tig + 8]);
                a[mt][3] = *reinterpret_cast<const uint*>(&ws_hi[ro + 8][kb + 2 * tig + 8]);
            }
            #pragma unroll
            for (int mt = 0; mt < 4; mt++)
                #pragma unroll
                for (int nt = 0; nt < 4; nt++) {
                    MMA16816(acc[mt][nt], a[mt], bh[nt]);
                    MMA16816(acc[mt][nt], a[mt], bl[nt]);
                }
            // A = w_lo : lo*hi
            #pragma unroll
            for (int mt = 0; mt < 4; mt++) {
                int ro = wo * 64 + mt * 16 + g;
                a[mt][0] = *reinterpret_cast<const uint*>(&ws_lo[ro][kb + 2 * tig]);
                a[mt][1] = *reinterpret_cast<const uint*>(&ws_lo[ro + 8][kb + 2 * tig]);
                a[mt][2] = *reinterpret_cast<const uint*>(&ws_lo[ro][kb + 2 * tig + 8]);
                a[mt][3] = *reinterpret_cast<const uint*>(&ws_lo[ro + 8][kb + 2 * tig + 8]);
            }
            #pragma unroll
            for (int mt = 0; mt < 4; mt++)
                #pragma unroll
                for (int nt = 0; nt < 4; nt++)
                    MMA16816(acc[mt][nt], a[mt], bh[nt]);
        }
    }

    // ---- epilogue: bias + relu + score partials ----
    const int hrow = wp >> 1;                 // this warp's h row within tile
    const int bh_idx = t * 2 + hrow;
    const int hloc = bh_idx & 63;

    float rowp = 0.f;
    float cp[4][2];
    #pragma unroll
    for (int nt = 0; nt < 4; nt++) { cp[nt][0] = 0.f; cp[nt][1] = 0.f; }

    #pragma unroll
    for (int mt = 0; mt < 4; mt++) {
        const int o  = half * 128 + wo * 64 + mt * 16 + g;
        const int o2 = o + 8;
        const float bias1 = __ldg(&b2[o]);
        const float bias2 = __ldg(&b2[o2]);
        const float wc1 = __ldg(&w_col[o * NN + hloc]);
        const float wc2 = __ldg(&w_col[o2 * NN + hloc]);
        #pragma unroll
        for (int nt = 0; nt < 4; nt++) {
            const int p  = wp * 32 + nt * 8 + 2 * tig;  // even, tile px
            const int w0 = p & 63;
            float2 wrA = __ldg(reinterpret_cast<const float2*>(&w_row[o * NN + w0]));
            float2 wrB = __ldg(reinterpret_cast<const float2*>(&w_row[o2 * NN + w0]));
            float r0 = fmaxf(acc[mt][nt][0] + bias1, 0.f);
            float r1 = fmaxf(acc[mt][nt][1] + bias1, 0.f);
            float r2 = fmaxf(acc[mt][nt][2] + bias2, 0.f);
            float r3 = fmaxf(acc[mt][nt][3] + bias2, 0.f);
            rowp += r0 * wrA.x + r1 * wrA.y + r2 * wrB.x + r3 * wrB.y;
            cp[nt][0] += r0 * wc1 + r2 * wc2;
            cp[nt][1] += r1 * wc1 + r3 * wc2;
        }
    }

    // rowp: whole warp shares h row -> warp reduce
    #pragma unroll
    for (int m = 16; m >= 1; m >>= 1)
        rowp += __shfl_xor_sync(0xffffffffu, rowp, m);
    if (lane == 0) atomicAdd(&rowred[hrow], rowp);

    // col partials: reduce over g (lane strides 4,8,16), lanes g==0 commit
    #pragma unroll
    for (int nt = 0; nt < 4; nt++) {
        #pragma unroll
        for (int q = 0; q < 2; q++) {
            cp[nt][q] += __shfl_xor_sync(0xffffffffu, cp[nt][q], 4);
            cp[nt][q] += __shfl_xor_sync(0xffffffffu, cp[nt][q], 8);
            cp[nt][q] += __shfl_xor_sync(0xffffffffu, cp[nt][q], 16);
        }
    }
    if (g == 0) {
        #pragma unroll
        for (int nt = 0; nt < 4; nt++) {
            int p = wp * 32 + nt * 8 + 2 * tig;
            atomicAdd(&colred[p & 63], cp[nt][0]);
            atomicAdd(&colred[(p + 1) & 63], cp[nt][1]);
        }
    }
    __syncthreads();

    if (tid < 2)
        g_rowpart[half * (BB * NN) + t * 2 + tid] = rowred[tid];
    if (tid < 64)
        g_cp[((size_t)half * 1024 + t) * NN + tid] = colred[tid];
}

// =====================================================================
// Kernel 3: combine partials into final scores
// =====================================================================
__global__ void combine_kernel(const float* __restrict__ b_row,
                               const float* __restrict__ b_col)
{
    int b = blockIdx.x;
    int w = threadIdx.x;
    float s = __ldg(&b_col[0]);
    #pragma unroll 4
    for (int tt = 0; tt < 32; tt++) {
        s += g_cp[(size_t)(b * 32 + tt) * NN + w];
        s += g_cp[(size_t)(1024 + b * 32 + tt) * NN + w];
    }
    g_colscore[b * NN + w] = s;
    int bh = b * NN + w;
    g_rowscore[bh] = g_rowpart[bh] + g_rowpart[BB * NN + bh] + __ldg(&b_row[0]);
}

// =====================================================================
// Kernel 4: differentiable bitonic sort -> permutation matrix P
// =====================================================================
#define PPAD 65
__global__ void __launch_bounds__(256) sort_kernel()
{
    __shared__ float P[NN * PPAD];
    __shared__ float xsh[NN];
    __shared__ float alph[32];
    __shared__ int   pa[32], pb[32];

    const int tid  = threadIdx.x;
    const int s    = blockIdx.x;
    const int kind = s >> 5;
    const int b    = s & 31;
    const float* sc = kind ? g_colscore : g_rowscore;

    if (tid < NN) xsh[tid] = sc[b * NN + tid];
    for (int idx = tid; idx < NN * NN; idx += 256) {
        int r = idx >> 6, c = idx & 63;
        P[r * PPAD + c] = (r == c) ? 1.f : 0.f;
    }
    __syncthreads();

    for (int blk = 0; blk < 6; blk++) {
        for (int lay = 0; lay <= blk; lay++) {
            int m = 1 << (blk - lay);
            if (tid < 32) {
                int q  = tid;
                int ix = ((q & ~(m - 1)) << 1) | (q & (m - 1));
                int a = ix, bidx = ix + m;
                if ((ix >> (blk + 1)) & 1) { int tswap = a; a = bidx; bidx = tswap; }
                pa[q] = a; pb[q] = bidx;
                float xa = xsh[a], xb = xsh[bidx];
                float al = atanf((xb - xa) * 50.f) * 0.31830988618379067f + 0.5f;
                alph[q] = al;
                xsh[a]    = al * xa + (1.f - al) * xb;
                xsh[bidx] = (1.f - al) * xa + al * xb;
            }
            __syncthreads();
            #pragma unroll
            for (int it = 0; it < 8; it++) {
                int idx = tid + it * 256;
                int r = idx >> 5, q = idx & 31;
                int a = pa[q], bidx = pb[q];
                float al = alph[q];
                float Pa = P[r * PPAD + a], Pb = P[r * PPAD + bidx];
                P[r * PPAD + a]    = al * Pa + (1.f - al) * Pb;
                P[r * PPAD + bidx] = (1.f - al) * Pa + al * Pb;
            }
            __syncthreads();
        }
    }

    for (int idx = tid; idx < NN * NN; idx += 256)
        g_P[(size_t)(kind * BB + b) * NN * NN + idx] = P[(idx >> 6) * PPAD + (idx & 63)];
}

// =====================================================================
// Kernel 5: out[b,c] = P_col * (P_row * X)^T     (one block per (b,c))
// =====================================================================
#define YPAD 68
struct ApplySmem {
    float Xs[NN * NN];
    float Prs[NN * PPAD];
    float Pcs[NN * PPAD];
    float Yt[NN * YPAD];
};

__global__ void __launch_bounds__(128) apply_kernel(
    const float* __restrict__ x, float* __restrict__ out)
{
    extern __shared__ unsigned char dyn_smem[];
    ApplySmem* sm = reinterpret_cast<ApplySmem*>(dyn_smem);

    const int tid = threadIdx.x;
    const int bc  = blockIdx.x;
    const int b   = bc >> 7;

    {
        const float4* xg = reinterpret_cast<const float4*>(x) + (size_t)bc * (NN * NN / 4);
        float4* Xs4 = reinterpret_cast<float4*>(sm->Xs);
        #pragma unroll
        for (int j = 0; j < 8; j++) Xs4[tid + j * 128] = xg[tid + j * 128];
    }
    {
        const float4* pr4 = reinterpret_cast<const float4*>(&g_P[(size_t)b * NN * NN]);
        const float4* pc4 = reinterpret_cast<const float4*>(&g_P[(size_t)(BB + b) * NN * NN]);
        #pragma unroll
        for (int j = 0; j < 8; j++) {
            int idx = tid + j * 128;
            int l = idx * 4, r = l >> 6, c = l & 63;
            float4 v = pr4[idx];
            float* d = &sm->Prs[r * PPAD + c];
            d[0] = v.x; d[1] = v.y; d[2] = v.z; d[3] = v.w;
            float4 u = pc4[idx];
            float* e = &sm->Pcs[r * PPAD + c];
            e[0] = u.x; e[1] = u.y; e[2] = u.z; e[3] = u.w;
        }
    }
    __syncthreads();

    const int ig = tid >> 4, kg = tid & 15;
    const int i0 = ig * 8,   k0 = kg * 4;

    ULL acc[8][2];
    #pragma unroll
    for (int ii = 0; ii < 8; ii++) { acc[ii][0] = 0ull; acc[ii][1] = 0ull; }

    #pragma unroll 4
    for (int j = 0; j < NN; j++) {
        const ULL* xp = reinterpret_cast<const ULL*>(&sm->Xs[j * NN + k0]);
        ULL xv0 = xp[0], xv1 = xp[1];
        #pragma unroll
        for (int ii = 0; ii < 8; ii++) {
            float p = sm->Prs[(i0 + ii) * PPAD + j];
            ULL pp = pack2(p, p);
            acc[ii][0] = fma2(xv0, pp, acc[ii][0]);
            acc[ii][1] = fma2(xv1, pp, acc[ii][1]);
        }
    }
    {
        float yv[8][4];
        #pragma unroll
        for (int ii = 0; ii < 8; ii++) {
            unpack2(acc[ii][0], yv[ii][0], yv[ii][1]);
            unpack2(acc[ii][1], yv[ii][2], yv[ii][3]);
        }
        #pragma unroll
        for (int kk = 0; kk < 4; kk++) {
            float4 v0 = make_float4(yv[0][kk], yv[1][kk], yv[2][kk], yv[3][kk]);
            float4 v1 = make_float4(yv[4][kk], yv[5][kk], yv[6][kk], yv[7][kk]);
            *reinterpret_cast<float4*>(&sm->Yt[(k0 + kk) * YPAD + i0])     = v0;
            *reinterpret_cast<float4*>(&sm->Yt[(k0 + kk) * YPAD + i0 + 4]) = v1;
        }
    }
    __syncthreads();

    #pragma unroll
    for (int ii = 0; ii < 8; ii++) { acc[ii][0] = 0ull; acc[ii][1] = 0ull; }

    #pragma unroll 4
    for (int j = 0; j < NN; j++) {
        const ULL* yp = reinterpret_cast<const ULL*>(&sm->Yt[j * YPAD + k0]);
        ULL yv0 = yp[0], yv1 = yp[1];
        #pragma unroll
        for (int ii = 0; ii < 8; ii++) {
            float p = sm->Pcs[(i0 + ii) * PPAD + j];
            ULL pp = pack2(p, p);
            acc[ii][0] = fma2(yv0, pp, acc[ii][0]);
            acc[ii][1] = fma2(yv1, pp, acc[ii][1]);
        }
    }

    float* og = out + (size_t)bc * NN * NN;
    #pragma unroll
    for (int ii = 0; ii < 8; ii++) {
        float o0, o1, o2, o3;
        unpack2(acc[ii][0], o0, o1);
        unpack2(acc[ii][1], o2, o3);
        *reinterpret_cast<float4*>(&og[(ii + i0) * NN + k0]) = make_float4(o0, o1, o2, o3);
    }
}

// =====================================================================
// launcher
// =====================================================================
extern "C" void kernel_launch(void* const* d_in, const int* in_sizes, int n_in,
                              void* d_out, int out_size)
{
    const float* x     = (const float*)d_in[0];
    const float* w1    = (const float*)d_in[1];
    const float* b1    = (const float*)d_in[2];
    const float* w2    = (const float*)d_in[3];
    const float* b2    = (const float*)d_in[4];
    const float* w_row = (const float*)d_in[5];
    const float* b_row = (const float*)d_in[6];
    const float* w_col = (const float*)d_in[7];
    const float* b_col = (const float*)d_in[8];
    float* out = (float*)d_out;

    const int apply_smem = (int)sizeof(ApplySmem);
    cudaFuncSetAttribute(apply_kernel, cudaFuncAttributeMaxDynamicSharedMemorySize, apply_smem);

    prep_w2_kernel<<<HID * HID / 256, 256>>>(w2);
    conv1_kernel<<<dim3(1024, 2), 256>>>(x, w1, b1);
    conv2_mma_kernel<<<dim3(1024, 2), 256>>>(b2, w_row, w_col);
    combine_kernel<<<BB, NN>>>(b_row, b_col);
    sort_kernel<<<2 * BB, 256>>>();
    apply_kernel<<<BB * CC, 128, apply_smem>>>(x, out);
}

// round 15
// speedup vs baseline: 1.1197x; 1.0231x over previous
#include <cuda_runtime.h>
#include <cuda_bf16.h>
#include <cstdint>

// Problem constants
#define BB   32
#define CC   128
#define NN   64
#define HID  256
#define NPX  (BB * NN * NN)        // 131072 pixels

typedef unsigned long long ULL;
typedef unsigned int uint;

// ---------- packed f32x2 helpers ----------
__device__ __forceinline__ ULL pack2(float a, float b) {
    ULL r;
    asm("mov.b64 %0, {%1, %2};" : "=l"(r) : "r"(__float_as_uint(a)), "r"(__float_as_uint(b)));
    return r;
}
__device__ __forceinline__ void unpack2(ULL v, float& a, float& b) {
    unsigned lo, hi;
    asm("mov.b64 {%0, %1}, %2;" : "=r"(lo), "=r"(hi) : "l"(v));
    a = __uint_as_float(lo); b = __uint_as_float(hi);
}
__device__ __forceinline__ ULL fma2(ULL a, ULL b, ULL c) {
    ULL d;
    asm("fma.rn.f32x2 %0, %1, %2, %3;" : "=l"(d) : "l"(a), "l"(b), "l"(c));
    return d;
}

// ---------- mma.sync m16n8k16 bf16 ----------
#define MMA16816(d, a, b) \
    asm volatile("mma.sync.aligned.m16n8k16.row.col.f32.bf16.bf16.f32 " \
                 "{%0,%1,%2,%3}, {%4,%5,%6,%7}, {%8,%9}, {%0,%1,%2,%3};" \
                 : "+f"((d)[0]), "+f"((d)[1]), "+f"((d)[2]), "+f"((d)[3]) \
                 : "r"((a)[0]), "r"((a)[1]), "r"((a)[2]), "r"((a)[3]), \
                   "r"((b)[0]), "r"((b)[1]))

// ---------- device scratch (no allocations allowed) ----------
__device__ __nv_bfloat16 g_hhi[(size_t)NPX * HID];    // 67 MB  h1 hi split, [px][k]
__device__ __nv_bfloat16 g_hlo[(size_t)NPX * HID];    // 67 MB  h1 lo split
__device__ __nv_bfloat16 g_w2hi[HID * HID];
__device__ __nv_bfloat16 g_w2lo[HID * HID];
__device__ float g_rowpart[2 * BB * NN];
__device__ float g_cp[2 * 1024 * NN];
__device__ float g_rowscore[BB * NN];
__device__ float g_colscore[BB * NN];
__device__ float g_P[2 * BB * NN * NN];

// =====================================================================
// Kernel 0: split w2 into bf16 hi/lo
// =====================================================================
__global__ void prep_w2_kernel(const float* __restrict__ w2)
{
    int i = blockIdx.x * 256 + threadIdx.x;
    if (i < HID * HID) {
        float f = w2[i];
        __nv_bfloat16 h = __float2bfloat16(f);
        g_w2hi[i] = h;
        g_w2lo[i] = __float2bfloat16(f - __bfloat162float(h));
    }
}

// =====================================================================
// Kernel 1: conv1 + relu -> split bf16 h1 in [px][k] layout.
// fp32x2 GEMM (proven round-11/12 structure).
// =====================================================================
#define CK  16
#define WTP 132

__global__ void __launch_bounds__(256, 2) conv1_kernel(
    const float* __restrict__ x, const float* __restrict__ w1,
    const float* __restrict__ b1)
{
    __shared__ float xs[CK][128];
    __shared__ float wts[CK][WTP];

    const int tid  = threadIdx.x;
    const int t    = blockIdx.x;
    const int half = blockIdx.y;
    const int og   = tid >> 4;
    const int pg   = tid & 15;
    const int obase = half * 128 + og * 8;

    const int bidx   = (t * 128) >> 12;
    const int binner = (t * 128) & 4095;
    const float* xb = x + ((size_t)bidx * CC) * 4096 + binner;

    const int f0 = tid, f1 = tid + 256;
    const int xc0 = f0 >> 5, xp0 = f0 & 31;
    const int xc1 = f1 >> 5, xp1 = f1 & 31;
    const int wo0 = f0 >> 2, wc0 = f0 & 3;
    const int wo1 = f1 >> 2, wc1 = f1 & 3;

    ULL acc[4][8];
    #pragma unroll
    for (int op = 0; op < 4; op++) {
        ULL p = pack2(__ldg(&b1[obase + op * 2]), __ldg(&b1[obase + op * 2 + 1]));
        #pragma unroll
        for (int q = 0; q < 8; q++) acc[op][q] = p;
    }

    float4 xr0 = *reinterpret_cast<const float4*>(&xb[(size_t)xc0 * 4096 + xp0 * 4]);
    float4 xr1 = *reinterpret_cast<const float4*>(&xb[(size_t)xc1 * 4096 + xp1 * 4]);
    float4 wr0 = *reinterpret_cast<const float4*>(&w1[(half * 128 + wo0) * CC + wc0 * 4]);
    float4 wr1 = *reinterpret_cast<const float4*>(&w1[(half * 128 + wo1) * CC + wc1 * 4]);

    for (int kc = 0; kc < CC / CK; kc++) {
        __syncthreads();
        *reinterpret_cast<float4*>(&xs[xc0][xp0 * 4]) = xr0;
        *reinterpret_cast<float4*>(&xs[xc1][xp1 * 4]) = xr1;
        wts[wc0 * 4 + 0][wo0] = wr0.x; wts[wc0 * 4 + 1][wo0] = wr0.y;
        wts[wc0 * 4 + 2][wo0] = wr0.z; wts[wc0 * 4 + 3][wo0] = wr0.w;
        wts[wc1 * 4 + 0][wo1] = wr1.x; wts[wc1 * 4 + 1][wo1] = wr1.y;
        wts[wc1 * 4 + 2][wo1] = wr1.z; wts[wc1 * 4 + 3][wo1] = wr1.w;
        __syncthreads();

        if (kc + 1 < CC / CK) {
            int k = (kc + 1) * CK;
            xr0 = *reinterpret_cast<const float4*>(&xb[(size_t)(k + xc0) * 4096 + xp0 * 4]);
            xr1 = *reinterpret_cast<const float4*>(&xb[(size_t)(k + xc1) * 4096 + xp1 * 4]);
            wr0 = *reinterpret_cast<const float4*>(&w1[(half * 128 + wo0) * CC + k + wc0 * 4]);
            wr1 = *reinterpret_cast<const float4*>(&w1[(half * 128 + wo1) * CC + k + wc1 * 4]);
        }

        #pragma unroll
        for (int c = 0; c < CK; c++) {
            ulonglong2 wa = *reinterpret_cast<const ulonglong2*>(&wts[c][og * 8]);
            ulonglong2 wb = *reinterpret_cast<const ulonglong2*>(&wts[c][og * 8 + 4]);
            float4 xa = *reinterpret_cast<const float4*>(&xs[c][pg * 4]);
            float4 xc = *reinterpret_cast<const float4*>(&xs[c][64 + pg * 4]);
            ULL xp[8];
            xp[0] = pack2(xa.x, xa.x); xp[1] = pack2(xa.y, xa.y);
            xp[2] = pack2(xa.z, xa.z); xp[3] = pack2(xa.w, xa.w);
            xp[4] = pack2(xc.x, xc.x); xp[5] = pack2(xc.y, xc.y);
            xp[6] = pack2(xc.z, xc.z); xp[7] = pack2(xc.w, xc.w);
            #pragma unroll
            for (int q = 0; q < 8; q++) {
                acc[0][q] = fma2(wa.x, xp[q], acc[0][q]);
                acc[1][q] = fma2(wa.y, xp[q], acc[1][q]);
                acc[2][q] = fma2(wb.x, xp[q], acc[2][q]);
                acc[3][q] = fma2(wb.y, xp[q], acc[3][q]);
            }
        }
    }

    // ---- epilogue: relu, split into bf16 hi/lo, store [px][k] ----
    float vals[8][8];
    #pragma unroll
    for (int op = 0; op < 4; op++) {
        #pragma unroll
        for (int q = 0; q < 8; q++) {
            float a, b;
            unpack2(acc[op][q], a, b);
            vals[q][op * 2]     = fmaxf(a, 0.f);
            vals[q][op * 2 + 1] = fmaxf(b, 0.f);
        }
    }
    #pragma unroll
    for (int q = 0; q < 8; q++) {
        size_t px = (size_t)t * 128 + pg * 4 + (q & 3) + (q >> 2) * 64;
        uint hi[4], lo[4];
        #pragma unroll
        for (int j = 0; j < 4; j++) {
            float f0v = vals[q][j * 2], f1v = vals[q][j * 2 + 1];
            __nv_bfloat16 h0 = __float2bfloat16(f0v);
            __nv_bfloat16 h1 = __float2bfloat16(f1v);
            __nv_bfloat162 hp; hp.x = h0; hp.y = h1;
            hi[j] = *reinterpret_cast<uint*>(&hp);
            __nv_bfloat162 lp;
            lp.x = __float2bfloat16(f0v - __bfloat162float(h0));
            lp.y = __float2bfloat16(f1v - __bfloat162float(h1));
            lo[j] = *reinterpret_cast<uint*>(&lp);
        }
        *reinterpret_cast<uint4*>(&g_hhi[px * HID + obase]) = make_uint4(hi[0], hi[1], hi[2], hi[3]);
        *reinterpret_cast<uint4*>(&g_hlo[px * HID + obase]) = make_uint4(lo[0], lo[1], lo[2], lo[3]);
    }
}

// =====================================================================
// Kernel 2: conv2 via mma.sync bf16 x3 splits + relu + score partials.
// 512 thr (16 warps), tile 128o x 128px; warp tile 32o x 32px.
// KCP=40 -> 80B row stride (16B-aligned for uint4 staging stores,
// conflict-free fragment LDS). 32 acc floats/thread -> no spills.
// =====================================================================
#define KC2  32
#define KCP  40

__global__ void __launch_bounds__(512, 1) conv2_mma_kernel(
    const float* __restrict__ b2,
    const float* __restrict__ w_row, const float* __restrict__ w_col)
{
    __shared__ __nv_bfloat16 hs_hi[128][KCP];
    __shared__ __nv_bfloat16 hs_lo[128][KCP];
    __shared__ __nv_bfloat16 ws_hi[128][KCP];
    __shared__ __nv_bfloat16 ws_lo[128][KCP];
    __shared__ float colred[64];
    __shared__ float rowred[2];

    const int tid  = threadIdx.x;
    const int t    = blockIdx.x;
    const int half = blockIdx.y;
    const int warp = tid >> 5;
    const int lane = tid & 31;
    const int g    = lane >> 2;
    const int tig  = lane & 3;
    const int wo   = warp >> 2;      // 0..3 -> o chunk of 32
    const int wp   = warp & 3;       // 0..3 -> px chunk of 32

    if (tid < 64) colred[tid] = 0.f;
    if (tid < 2)  rowred[tid] = 0.f;

    const size_t pxbase = (size_t)t * 128;

    float acc[2][4][4];
    #pragma unroll
    for (int mt = 0; mt < 2; mt++)
        #pragma unroll
        for (int nt = 0; nt < 4; nt++)
            #pragma unroll
            for (int i = 0; i < 4; i++) acc[mt][nt][i] = 0.f;

    const int srow = tid >> 2;       // 0..127
    const int sseg = tid & 3;        // 8-element (16B) segment
    const size_t hoff_base = (pxbase + srow) * HID + sseg * 8;
    const size_t woff_base = (size_t)(half * 128 + srow) * HID + sseg * 8;

    uint4 r_hh = *reinterpret_cast<const uint4*>(&g_hhi[hoff_base]);
    uint4 r_hl = *reinterpret_cast<const uint4*>(&g_hlo[hoff_base]);
    uint4 r_wh = *reinterpret_cast<const uint4*>(&g_w2hi[woff_base]);
    uint4 r_wl = *reinterpret_cast<const uint4*>(&g_w2lo[woff_base]);

    for (int kc = 0; kc < HID / KC2; kc++) {
        if (kc > 0) __syncthreads();
        *reinterpret_cast<uint4*>(&hs_hi[srow][sseg * 8]) = r_hh;
        *reinterpret_cast<uint4*>(&hs_lo[srow][sseg * 8]) = r_hl;
        *reinterpret_cast<uint4*>(&ws_hi[srow][sseg * 8]) = r_wh;
        *reinterpret_cast<uint4*>(&ws_lo[srow][sseg * 8]) = r_wl;
        __syncthreads();

        if (kc + 1 < HID / KC2) {
            const size_t koff = (size_t)(kc + 1) * KC2;
            r_hh = *reinterpret_cast<const uint4*>(&g_hhi[hoff_base + koff]);
            r_hl = *reinterpret_cast<const uint4*>(&g_hlo[hoff_base + koff]);
            r_wh = *reinterpret_cast<const uint4*>(&g_w2hi[woff_base + koff]);
            r_wl = *reinterpret_cast<const uint4*>(&g_w2lo[woff_base + koff]);
        }

        #pragma unroll
        for (int kk = 0; kk < 2; kk++) {
            const int kb = kk * 16;
            uint a[2][4], bh[4][2], bl[4][2];
            #pragma unroll
            for (int nt = 0; nt < 4; nt++) {
                int rp = wp * 32 + nt * 8 + g;
                bh[nt][0] = *reinterpret_cast<const uint*>(&hs_hi[rp][kb + 2 * tig]);
                bh[nt][1] = *reinterpret_cast<const uint*>(&hs_hi[rp][kb + 2 * tig + 8]);
                bl[nt][0] = *reinterpret_cast<const uint*>(&hs_lo[rp][kb + 2 * tig]);
                bl[nt][1] = *reinterpret_cast<const uint*>(&hs_lo[rp][kb + 2 * tig + 8]);
            }
            // A = w_hi : hi*hi and hi*lo
            #pragma unroll
            for (int mt = 0; mt < 2; mt++) {
                int ro = wo * 32 + mt * 16 + g;
                a[mt][0] = *reinterpret_cast<const uint*>(&ws_hi[ro][kb + 2 * tig]);
                a[mt][1] = *reinterpret_cast<const uint*>(&ws_hi[ro + 8][kb + 2 * tig]);
                a[mt][2] = *reinterpret_cast<const uint*>(&ws_hi[ro][kb + 2 * tig + 8]);
                a[mt][3] = *reinterpret_cast<const uint*>(&ws_hi[ro + 8][kb + 2 * tig + 8]);
            }
            #pragma unroll
            for (int mt = 0; mt < 2; mt++)
                #pragma unroll
                for (int nt = 0; nt < 4; nt++) {
                    MMA16816(acc[mt][nt], a[mt], bh[nt]);
                    MMA16816(acc[mt][nt], a[mt], bl[nt]);
                }
            // A = w_lo : lo*hi
            #pragma unroll
            for (int mt = 0; mt < 2; mt++) {
                int ro = wo * 32 + mt * 16 + g;
                a[mt][0] = *reinterpret_cast<const uint*>(&ws_lo[ro][kb + 2 * tig]);
                a[mt][1] = *reinterpret_cast<const uint*>(&ws_lo[ro + 8][kb + 2 * tig]);
                a[mt][2] = *reinterpret_cast<const uint*>(&ws_lo[ro][kb + 2 * tig + 8]);
                a[mt][3] = *reinterpret_cast<const uint*>(&ws_lo[ro + 8][kb + 2 * tig + 8]);
            }
            #pragma unroll
            for (int mt = 0; mt < 2; mt++)
                #pragma unroll
                for (int nt = 0; nt < 4; nt++)
                    MMA16816(acc[mt][nt], a[mt], bh[nt]);
        }
    }

    // ---- epilogue: bias + relu + score partials ----
    const int hrow = (wp >= 2) ? 1 : 0;
    const int bh_idx = t * 2 + hrow;
    const int hloc = bh_idx & 63;

    float rowp = 0.f;
    float cp[4][2];
    #pragma unroll
    for (int nt = 0; nt < 4; nt++) { cp[nt][0] = 0.f; cp[nt][1] = 0.f; }

    #pragma unroll
    for (int mt = 0; mt < 2; mt++) {
        const int o  = half * 128 + wo * 32 + mt * 16 + g;
        const int o2 = o + 8;
        const float bias1 = __ldg(&b2[o]);
        const float bias2 = __ldg(&b2[o2]);
        const float wc1 = __ldg(&w_col[o * NN + hloc]);
        const float wc2 = __ldg(&w_col[o2 * NN + hloc]);
        #pragma unroll
        for (int nt = 0; nt < 4; nt++) {
            const int p  = wp * 32 + nt * 8 + 2 * tig;
            const int w0 = p & 63;
            float2 wrA = __ldg(reinterpret_cast<const float2*>(&w_row[o * NN + w0]));
            float2 wrB = __ldg(reinterpret_cast<const float2*>(&w_row[o2 * NN + w0]));
            float r0 = fmaxf(acc[mt][nt][0] + bias1, 0.f);
            float r1 = fmaxf(acc[mt][nt][1] + bias1, 0.f);
            float r2 = fmaxf(acc[mt][nt][2] + bias2, 0.f);
            float r3 = fmaxf(acc[mt][nt][3] + bias2, 0.f);
            rowp += r0 * wrA.x + r1 * wrA.y + r2 * wrB.x + r3 * wrB.y;
            cp[nt][0] += r0 * wc1 + r2 * wc2;
            cp[nt][1] += r1 * wc1 + r3 * wc2;
        }
    }

    #pragma unroll
    for (int m = 16; m >= 1; m >>= 1)
        rowp += __shfl_xor_sync(0xffffffffu, rowp, m);
    if (lane == 0) atomicAdd(&rowred[hrow], rowp);

    #pragma unroll
    for (int nt = 0; nt < 4; nt++) {
        #pragma unroll
        for (int q = 0; q < 2; q++) {
            cp[nt][q] += __shfl_xor_sync(0xffffffffu, cp[nt][q], 4);
            cp[nt][q] += __shfl_xor_sync(0xffffffffu, cp[nt][q], 8);
            cp[nt][q] += __shfl_xor_sync(0xffffffffu, cp[nt][q], 16);
        }
    }
    if (g == 0) {
        #pragma unroll
        for (int nt = 0; nt < 4; nt++) {
            int p = wp * 32 + nt * 8 + 2 * tig;
            atomicAdd(&colred[p & 63], cp[nt][0]);
            atomicAdd(&colred[(p + 1) & 63], cp[nt][1]);
        }
    }
    __syncthreads();

    if (tid < 2)
        g_rowpart[half * (BB * NN) + t * 2 + tid] = rowred[tid];
    if (tid < 64)
        g_cp[((size_t)half * 1024 + t) * NN + tid] = colred[tid];
}

// =====================================================================
// Kernel 3: combine partials into final scores
// =====================================================================
__global__ void combine_kernel(const float* __restrict__ b_row,
                               const float* __restrict__ b_col)
{
    int b = blockIdx.x;
    int w = threadIdx.x;
    float s = __ldg(&b_col[0]);
    #pragma unroll 4
    for (int tt = 0; tt < 32; tt++) {
        s += g_cp[(size_t)(b * 32 + tt) * NN + w];
        s += g_cp[(size_t)(1024 + b * 32 + tt) * NN + w];
    }
    g_colscore[b * NN + w] = s;
    int bh = b * NN + w;
    g_rowscore[bh] = g_rowpart[bh] + g_rowpart[BB * NN + bh] + __ldg(&b_row[0]);
}

// =====================================================================
// Kernel 4: differentiable bitonic sort -> permutation matrix P
// =====================================================================
#define PPAD 65
__global__ void __launch_bounds__(256) sort_kernel()
{
    __shared__ float P[NN * PPAD];
    __shared__ float xsh[NN];
    __shared__ float alph[32];
    __shared__ int   pa[32], pb[32];

    const int tid  = threadIdx.x;
    const int s    = blockIdx.x;
    const int kind = s >> 5;
    const int b    = s & 31;
    const float* sc = kind ? g_colscore : g_rowscore;

    if (tid < NN) xsh[tid] = sc[b * NN + tid];
    for (int idx = tid; idx < NN * NN; idx += 256) {
        int r = idx >> 6, c = idx & 63;
        P[r * PPAD + c] = (r == c) ? 1.f : 0.f;
    }
    __syncthreads();

    for (int blk = 0; blk < 6; blk++) {
        for (int lay = 0; lay <= blk; lay++) {
            int m = 1 << (blk - lay);
            if (tid < 32) {
                int q  = tid;
                int ix = ((q & ~(m - 1)) << 1) | (q & (m - 1));
                int a = ix, bidx = ix + m;
                if ((ix >> (blk + 1)) & 1) { int tswap = a; a = bidx; bidx = tswap; }
                pa[q] = a; pb[q] = bidx;
                float xa = xsh[a], xb = xsh[bidx];
                float al = atanf((xb - xa) * 50.f) * 0.31830988618379067f + 0.5f;
                alph[q] = al;
                xsh[a]    = al * xa + (1.f - al) * xb;
                xsh[bidx] = (1.f - al) * xa + al * xb;
            }
            __syncthreads();
            #pragma unroll
            for (int it = 0; it < 8; it++) {
                int idx = tid + it * 256;
                int r = idx >> 5, q = idx & 31;
                int a = pa[q], bidx = pb[q];
                float al = alph[q];
                float Pa = P[r * PPAD + a], Pb = P[r * PPAD + bidx];
                P[r * PPAD + a]    = al * Pa + (1.f - al) * Pb;
                P[r * PPAD + bidx] = (1.f - al) * Pa + al * Pb;
            }
            __syncthreads();
        }
    }

    for (int idx = tid; idx < NN * NN; idx += 256)
        g_P[(size_t)(kind * BB + b) * NN * NN + idx] = P[(idx >> 6) * PPAD + (idx & 63)];
}

// =====================================================================
// Kernel 5: out[b,c] = P_col * (P_row * X)^T     (one block per (b,c))
// =====================================================================
#define YPAD 68
struct ApplySmem {
    float Xs[NN * NN];
    float Prs[NN * PPAD];
    float Pcs[NN * PPAD];
    float Yt[NN * YPAD];
};

__global__ void __launch_bounds__(128) apply_kernel(
    const float* __restrict__ x, float* __restrict__ out)
{
    extern __shared__ unsigned char dyn_smem[];
    ApplySmem* sm = reinterpret_cast<ApplySmem*>(dyn_smem);

    const int tid = threadIdx.x;
    const int bc  = blockIdx.x;
    const int b   = bc >> 7;

    {
        const float4* xg = reinterpret_cast<const float4*>(x) + (size_t)bc * (NN * NN / 4);
        float4* Xs4 = reinterpret_cast<float4*>(sm->Xs);
        #pragma unroll
        for (int j = 0; j < 8; j++) Xs4[tid + j * 128] = xg[tid + j * 128];
    }
    {
        const float4* pr4 = reinterpret_cast<const float4*>(&g_P[(size_t)b * NN * NN]);
        const float4* pc4 = reinterpret_cast<const float4*>(&g_P[(size_t)(BB + b) * NN * NN]);
        #pragma unroll
        for (int j = 0; j < 8; j++) {
            int idx = tid + j * 128;
            int l = idx * 4, r = l >> 6, c = l & 63;
            float4 v = pr4[idx];
            float* d = &sm->Prs[r * PPAD + c];
            d[0] = v.x; d[1] = v.y; d[2] = v.z; d[3] = v.w;
            float4 u = pc4[idx];
            float* e = &sm->Pcs[r * PPAD + c];
            e[0] = u.x; e[1] = u.y; e[2] = u.z; e[3] = u.w;
        }
    }
    __syncthreads();

    const int ig = tid >> 4, kg = tid & 15;
    const int i0 = ig * 8,   k0 = kg * 4;

    ULL acc[8][2];
    #pragma unroll
    for (int ii = 0; ii < 8; ii++) { acc[ii][0] = 0ull; acc[ii][1] = 0ull; }

    #pragma unroll 4
    for (int j = 0; j < NN; j++) {
        const ULL* xp = reinterpret_cast<const ULL*>(&sm->Xs[j * NN + k0]);
        ULL xv0 = xp[0], xv1 = xp[1];
        #pragma unroll
        for (int ii = 0; ii < 8; ii++) {
            float p = sm->Prs[(i0 + ii) * PPAD + j];
            ULL pp = pack2(p, p);
            acc[ii][0] = fma2(xv0, pp, acc[ii][0]);
            acc[ii][1] = fma2(xv1, pp, acc[ii][1]);
        }
    }
    {
        float yv[8][4];
        #pragma unroll
        for (int ii = 0; ii < 8; ii++) {
            unpack2(acc[ii][0], yv[ii][0], yv[ii][1]);
            unpack2(acc[ii][1], yv[ii][2], yv[ii][3]);
        }
        #pragma unroll
        for (int kk = 0; kk < 4; kk++) {
            float4 v0 = make_float4(yv[0][kk], yv[1][kk], yv[2][kk], yv[3][kk]);
            float4 v1 = make_float4(yv[4][kk], yv[5][kk], yv[6][kk], yv[7][kk]);
            *reinterpret_cast<float4*>(&sm->Yt[(k0 + kk) * YPAD + i0])     = v0;
            *reinterpret_cast<float4*>(&sm->Yt[(k0 + kk) * YPAD + i0 + 4]) = v1;
        }
    }
    __syncthreads();

    #pragma unroll
    for (int ii = 0; ii < 8; ii++) { acc[ii][0] = 0ull; acc[ii][1] = 0ull; }

    #pragma unroll 4
    for (int j = 0; j < NN; j++) {
        const ULL* yp = reinterpret_cast<const ULL*>(&sm->Yt[j * YPAD + k0]);
        ULL yv0 = yp[0], yv1 = yp[1];
        #pragma unroll
        for (int ii = 0; ii < 8; ii++) {
            float p = sm->Pcs[(i0 + ii) * PPAD + j];
            ULL pp = pack2(p, p);
            acc[ii][0] = fma2(yv0, pp, acc[ii][0]);
            acc[ii][1] = fma2(yv1, pp, acc[ii][1]);
        }
    }

    float* og = out + (size_t)bc * NN * NN;
    #pragma unroll
    for (int ii = 0; ii < 8; ii++) {
        float o0, o1, o2, o3;
        unpack2(acc[ii][0], o0, o1);
        unpack2(acc[ii][1], o2, o3);
        *reinterpret_cast<float4*>(&og[(ii + i0) * NN + k0]) = make_float4(o0, o1, o2, o3);
    }
}

// =====================================================================
// launcher
// =====================================================================
extern "C" void kernel_launch(void* const* d_in, const int* in_sizes, int n_in,
                              void* d_out, int out_size)
{
    const float* x     = (const float*)d_in[0];
    const float* w1    = (const float*)d_in[1];
    const float* b1    = (const float*)d_in[2];
    const float* w2    = (const float*)d_in[3];
    const float* b2    = (const float*)d_in[4];
    const float* w_row = (const float*)d_in[5];
    const float* b_row = (const float*)d_in[6];
    const float* w_col = (const float*)d_in[7];
    const float* b_col = (const float*)d_in[8];
    float* out = (float*)d_out;

    const int apply_smem = (int)sizeof(ApplySmem);
    cudaFuncSetAttribute(apply_kernel, cudaFuncAttributeMaxDynamicSharedMemorySize, apply_smem);

    prep_w2_kernel<<<HID * HID / 256, 256>>>(w2);
    conv1_kernel<<<dim3(1024, 2), 256>>>(x, w1, b1);
    conv2_mma_kernel<<<dim3(1024, 2), 512>>>(b2, w_row, w_col);
    combine_kernel<<<BB, NN>>>(b_row, b_col);
    sort_kernel<<<2 * BB, 256>>>();
    apply_kernel<<<BB * CC, 128, apply_smem>>>(x, out);
}

// round 16
// speedup vs baseline: 1.1597x; 1.0357x over previous
#include <cuda_runtime.h>
#include <cuda_bf16.h>
#include <cstdint>

// Problem constants
#define BB   32
#define CC   128
#define NN   64
#define HID  256
#define NPX  (BB * NN * NN)        // 131072 pixels

typedef unsigned long long ULL;
typedef unsigned int uint;

// ---------- packed f32x2 helpers ----------
__device__ __forceinline__ ULL pack2(float a, float b) {
    ULL r;
    asm("mov.b64 %0, {%1, %2};" : "=l"(r) : "r"(__float_as_uint(a)), "r"(__float_as_uint(b)));
    return r;
}
__device__ __forceinline__ void unpack2(ULL v, float& a, float& b) {
    unsigned lo, hi;
    asm("mov.b64 {%0, %1}, %2;" : "=r"(lo), "=r"(hi) : "l"(v));
    a = __uint_as_float(lo); b = __uint_as_float(hi);
}
__device__ __forceinline__ ULL fma2(ULL a, ULL b, ULL c) {
    ULL d;
    asm("fma.rn.f32x2 %0, %1, %2, %3;" : "=l"(d) : "l"(a), "l"(b), "l"(c));
    return d;
}

// ---------- mma.sync m16n8k16 bf16 ----------
#define MMA16816(d, a, b) \
    asm volatile("mma.sync.aligned.m16n8k16.row.col.f32.bf16.bf16.f32 " \
                 "{%0,%1,%2,%3}, {%4,%5,%6,%7}, {%8,%9}, {%0,%1,%2,%3};" \
                 : "+f"((d)[0]), "+f"((d)[1]), "+f"((d)[2]), "+f"((d)[3]) \
                 : "r"((a)[0]), "r"((a)[1]), "r"((a)[2]), "r"((a)[3]), \
                   "r"((b)[0]), "r"((b)[1]))

// ---------- cp.async ----------
__device__ __forceinline__ uint smem_u32(const void* p) {
    return (uint)__cvta_generic_to_shared(p);
}
#define CP_ASYNC16(dst, src) \
    asm volatile("cp.async.cg.shared.global [%0], [%1], 16;" :: "r"(dst), "l"(src))
#define CP_COMMIT() asm volatile("cp.async.commit_group;" ::: "memory")
#define CP_WAIT0()  asm volatile("cp.async.wait_group 0;" ::: "memory")

// ---------- device scratch (no allocations allowed) ----------
__device__ __nv_bfloat16 g_hhi[(size_t)NPX * HID];    // 67 MB  h1 hi split, [px][k]
__device__ __nv_bfloat16 g_hlo[(size_t)NPX * HID];    // 67 MB  h1 lo split
__device__ __nv_bfloat16 g_w2hi[HID * HID];
__device__ __nv_bfloat16 g_w2lo[HID * HID];
__device__ float g_rowpart[2 * BB * NN];
__device__ float g_cp[2 * 1024 * NN];
__device__ float g_rowscore[BB * NN];
__device__ float g_colscore[BB * NN];
__device__ float g_P[2 * BB * NN * NN];

// =====================================================================
// Kernel 0: split w2 into bf16 hi/lo
// =====================================================================
__global__ void prep_w2_kernel(const float* __restrict__ w2)
{
    int i = blockIdx.x * 256 + threadIdx.x;
    if (i < HID * HID) {
        float f = w2[i];
        __nv_bfloat16 h = __float2bfloat16(f);
        g_w2hi[i] = h;
        g_w2lo[i] = __float2bfloat16(f - __bfloat162float(h));
    }
}

// =====================================================================
// Kernel 1: conv1 + relu -> split bf16 h1 in [px][k] layout.
// fp32x2 GEMM (proven round-11/12 structure).
// =====================================================================
#define CK  16
#define WTP 132

__global__ void __launch_bounds__(256, 2) conv1_kernel(
    const float* __restrict__ x, const float* __restrict__ w1,
    const float* __restrict__ b1)
{
    __shared__ float xs[CK][128];
    __shared__ float wts[CK][WTP];

    const int tid  = threadIdx.x;
    const int t    = blockIdx.x;
    const int half = blockIdx.y;
    const int og   = tid >> 4;
    const int pg   = tid & 15;
    const int obase = half * 128 + og * 8;

    const int bidx   = (t * 128) >> 12;
    const int binner = (t * 128) & 4095;
    const float* xb = x + ((size_t)bidx * CC) * 4096 + binner;

    const int f0 = tid, f1 = tid + 256;
    const int xc0 = f0 >> 5, xp0 = f0 & 31;
    const int xc1 = f1 >> 5, xp1 = f1 & 31;
    const int wo0 = f0 >> 2, wc0 = f0 & 3;
    const int wo1 = f1 >> 2, wc1 = f1 & 3;

    ULL acc[4][8];
    #pragma unroll
    for (int op = 0; op < 4; op++) {
        ULL p = pack2(__ldg(&b1[obase + op * 2]), __ldg(&b1[obase + op * 2 + 1]));
        #pragma unroll
        for (int q = 0; q < 8; q++) acc[op][q] = p;
    }

    float4 xr0 = *reinterpret_cast<const float4*>(&xb[(size_t)xc0 * 4096 + xp0 * 4]);
    float4 xr1 = *reinterpret_cast<const float4*>(&xb[(size_t)xc1 * 4096 + xp1 * 4]);
    float4 wr0 = *reinterpret_cast<const float4*>(&w1[(half * 128 + wo0) * CC + wc0 * 4]);
    float4 wr1 = *reinterpret_cast<const float4*>(&w1[(half * 128 + wo1) * CC + wc1 * 4]);

    for (int kc = 0; kc < CC / CK; kc++) {
        __syncthreads();
        *reinterpret_cast<float4*>(&xs[xc0][xp0 * 4]) = xr0;
        *reinterpret_cast<float4*>(&xs[xc1][xp1 * 4]) = xr1;
        wts[wc0 * 4 + 0][wo0] = wr0.x; wts[wc0 * 4 + 1][wo0] = wr0.y;
        wts[wc0 * 4 + 2][wo0] = wr0.z; wts[wc0 * 4 + 3][wo0] = wr0.w;
        wts[wc1 * 4 + 0][wo1] = wr1.x; wts[wc1 * 4 + 1][wo1] = wr1.y;
        wts[wc1 * 4 + 2][wo1] = wr1.z; wts[wc1 * 4 + 3][wo1] = wr1.w;
        __syncthreads();

        if (kc + 1 < CC / CK) {
            int k = (kc + 1) * CK;
            xr0 = *reinterpret_cast<const float4*>(&xb[(size_t)(k + xc0) * 4096 + xp0 * 4]);
            xr1 = *reinterpret_cast<const float4*>(&xb[(size_t)(k + xc1) * 4096 + xp1 * 4]);
            wr0 = *reinterpret_cast<const float4*>(&w1[(half * 128 + wo0) * CC + k + wc0 * 4]);
            wr1 = *reinterpret_cast<const float4*>(&w1[(half * 128 + wo1) * CC + k + wc1 * 4]);
        }

        #pragma unroll
        for (int c = 0; c < CK; c++) {
            ulonglong2 wa = *reinterpret_cast<const ulonglong2*>(&wts[c][og * 8]);
            ulonglong2 wb = *reinterpret_cast<const ulonglong2*>(&wts[c][og * 8 + 4]);
            float4 xa = *reinterpret_cast<const float4*>(&xs[c][pg * 4]);
            float4 xc = *reinterpret_cast<const float4*>(&xs[c][64 + pg * 4]);
            ULL xp[8];
            xp[0] = pack2(xa.x, xa.x); xp[1] = pack2(xa.y, xa.y);
            xp[2] = pack2(xa.z, xa.z); xp[3] = pack2(xa.w, xa.w);
            xp[4] = pack2(xc.x, xc.x); xp[5] = pack2(xc.y, xc.y);
            xp[6] = pack2(xc.z, xc.z); xp[7] = pack2(xc.w, xc.w);
            #pragma unroll
            for (int q = 0; q < 8; q++) {
                acc[0][q] = fma2(wa.x, xp[q], acc[0][q]);
                acc[1][q] = fma2(wa.y, xp[q], acc[1][q]);
                acc[2][q] = fma2(wb.x, xp[q], acc[2][q]);
                acc[3][q] = fma2(wb.y, xp[q], acc[3][q]);
            }
        }
    }

    // ---- epilogue: relu, split into bf16 hi/lo, store [px][k] ----
    float vals[8][8];
    #pragma unroll
    for (int op = 0; op < 4; op++) {
        #pragma unroll
        for (int q = 0; q < 8; q++) {
            float a, b;
            unpack2(acc[op][q], a, b);
            vals[q][op * 2]     = fmaxf(a, 0.f);
            vals[q][op * 2 + 1] = fmaxf(b, 0.f);
        }
    }
    #pragma unroll
    for (int q = 0; q < 8; q++) {
        size_t px = (size_t)t * 128 + pg * 4 + (q & 3) + (q >> 2) * 64;
        uint hi[4], lo[4];
        #pragma unroll
        for (int j = 0; j < 4; j++) {
            float f0v = vals[q][j * 2], f1v = vals[q][j * 2 + 1];
            __nv_bfloat16 h0 = __float2bfloat16(f0v);
            __nv_bfloat16 h1 = __float2bfloat16(f1v);
            __nv_bfloat162 hp; hp.x = h0; hp.y = h1;
            hi[j] = *reinterpret_cast<uint*>(&hp);
            __nv_bfloat162 lp;
            lp.x = __float2bfloat16(f0v - __bfloat162float(h0));
            lp.y = __float2bfloat16(f1v - __bfloat162float(h1));
            lo[j] = *reinterpret_cast<uint*>(&lp);
        }
        *reinterpret_cast<uint4*>(&g_hhi[px * HID + obase]) = make_uint4(hi[0], hi[1], hi[2], hi[3]);
        *reinterpret_cast<uint4*>(&g_hlo[px * HID + obase]) = make_uint4(lo[0], lo[1], lo[2], lo[3]);
    }
}

// =====================================================================
// Kernel 2: conv2 via mma.sync bf16 x3 splits + relu + score partials.
// 512 thr (16 warps), tile 128o x 128px; warp tile 32o x 32px.
// cp.async double-buffered staging (one barrier per chunk, loads overlap MMA).
// =====================================================================
#define KC2  32
#define KCP  40     // 80B row stride: 16B-aligned, conflict-free fragment LDS

__global__ void __launch_bounds__(512, 1) conv2_mma_kernel(
    const float* __restrict__ b2,
    const float* __restrict__ w_row, const float* __restrict__ w_col)
{
    __shared__ __align__(16) __nv_bfloat16 hs_hi[2][128][KCP];
    __shared__ __align__(16) __nv_bfloat16 hs_lo[2][128][KCP];
    __shared__ __align__(16) __nv_bfloat16 ws_hi[2][128][KCP];
    __shared__ __align__(16) __nv_bfloat16 ws_lo[2][128][KCP];
    __shared__ float colred[64];
    __shared__ float rowred[2];

    const int tid  = threadIdx.x;
    const int t    = blockIdx.x;
    const int half = blockIdx.y;
    const int warp = tid >> 5;
    const int lane = tid & 31;
    const int g    = lane >> 2;
    const int tig  = lane & 3;
    const int wo   = warp >> 2;      // 0..3 -> o chunk of 32
    const int wp   = warp & 3;       // 0..3 -> px chunk of 32

    if (tid < 64) colred[tid] = 0.f;
    if (tid < 2)  rowred[tid] = 0.f;

    const size_t pxbase = (size_t)t * 128;

    float acc[2][4][4];
    #pragma unroll
    for (int mt = 0; mt < 2; mt++)
        #pragma unroll
        for (int nt = 0; nt < 4; nt++)
            #pragma unroll
            for (int i = 0; i < 4; i++) acc[mt][nt][i] = 0.f;

    const int srow = tid >> 2;       // 0..127
    const int sseg = tid & 3;        // 16B segment
    const size_t hoff_base = (pxbase + srow) * HID + sseg * 8;
    const size_t woff_base = (size_t)(half * 128 + srow) * HID + sseg * 8;

    // prologue: stage chunk 0 into buffer 0
    {
        CP_ASYNC16(smem_u32(&hs_hi[0][srow][sseg * 8]), &g_hhi[hoff_base]);
        CP_ASYNC16(smem_u32(&hs_lo[0][srow][sseg * 8]), &g_hlo[hoff_base]);
        CP_ASYNC16(smem_u32(&ws_hi[0][srow][sseg * 8]), &g_w2hi[woff_base]);
        CP_ASYNC16(smem_u32(&ws_lo[0][srow][sseg * 8]), &g_w2lo[woff_base]);
        CP_COMMIT();
    }

    const int NCHUNK = HID / KC2;    // 8
    for (int kc = 0; kc < NCHUNK; kc++) {
        CP_WAIT0();
        __syncthreads();             // chunk kc staged; prev compute done

        if (kc + 1 < NCHUNK) {       // stage next chunk into other buffer
            const int nb = (kc + 1) & 1;
            const size_t koff = (size_t)(kc + 1) * KC2;
            CP_ASYNC16(smem_u32(&hs_hi[nb][srow][sseg * 8]), &g_hhi[hoff_base + koff]);
            CP_ASYNC16(smem_u32(&hs_lo[nb][srow][sseg * 8]), &g_hlo[hoff_base + koff]);
            CP_ASYNC16(smem_u32(&ws_hi[nb][srow][sseg * 8]), &g_w2hi[woff_base + koff]);
            CP_ASYNC16(smem_u32(&ws_lo[nb][srow][sseg * 8]), &g_w2lo[woff_base + koff]);
            CP_COMMIT();
        }

        const int buf = kc & 1;
        #pragma unroll
        for (int kk = 0; kk < 2; kk++) {
            const int kb = kk * 16;
            uint a[2][4], bh[4][2], bl[4][2];
            #pragma unroll
            for (int nt = 0; nt < 4; nt++) {
                int rp = wp * 32 + nt * 8 + g;
                bh[nt][0] = *reinterpret_cast<const uint*>(&hs_hi[buf][rp][kb + 2 * tig]);
                bh[nt][1] = *reinterpret_cast<const uint*>(&hs_hi[buf][rp][kb + 2 * tig + 8]);
                bl[nt][0] = *reinterpret_cast<const uint*>(&hs_lo[buf][rp][kb + 2 * tig]);
                bl[nt][1] = *reinterpret_cast<const uint*>(&hs_lo[buf][rp][kb + 2 * tig + 8]);
            }
            // A = w_hi : hi*hi and hi*lo
            #pragma unroll
            for (int mt = 0; mt < 2; mt++) {
                int ro = wo * 32 + mt * 16 + g;
                a[mt][0] = *reinterpret_cast<const uint*>(&ws_hi[buf][ro][kb + 2 * tig]);
                a[mt][1] = *reinterpret_cast<const uint*>(&ws_hi[buf][ro + 8][kb + 2 * tig]);
                a[mt][2] = *reinterpret_cast<const uint*>(&ws_hi[buf][ro][kb + 2 * tig + 8]);
                a[mt][3] = *reinterpret_cast<const uint*>(&ws_hi[buf][ro + 8][kb + 2 * tig + 8]);
            }
            #pragma unroll
            for (int mt = 0; mt < 2; mt++)
                #pragma unroll
                for (int nt = 0; nt < 4; nt++) {
                    MMA16816(acc[mt][nt], a[mt], bh[nt]);
                    MMA16816(acc[mt][nt], a[mt], bl[nt]);
                }
            // A = w_lo : lo*hi
            #pragma unroll
            for (int mt = 0; mt < 2; mt++) {
                int ro = wo * 32 + mt * 16 + g;
                a[mt][0] = *reinterpret_cast<const uint*>(&ws_lo[buf][ro][kb + 2 * tig]);
                a[mt][1] = *reinterpret_cast<const uint*>(&ws_lo[buf][ro + 8][kb + 2 * tig]);
                a[mt][2] = *reinterpret_cast<const uint*>(&ws_lo[buf][ro][kb + 2 * tig + 8]);
                a[mt][3] = *reinterpret_cast<const uint*>(&ws_lo[buf][ro + 8][kb + 2 * tig + 8]);
            }
            #pragma unroll
            for (int mt = 0; mt < 2; mt++)
                #pragma unroll
                for (int nt = 0; nt < 4; nt++)
                    MMA16816(acc[mt][nt], a[mt], bh[nt]);
        }
    }

    // ---- epilogue: bias + relu + score partials ----
    const int hrow = (wp >= 2) ? 1 : 0;
    const int bh_idx = t * 2 + hrow;
    const int hloc = bh_idx & 63;

    float rowp = 0.f;
    float cp[4][2];
    #pragma unroll
    for (int nt = 0; nt < 4; nt++) { cp[nt][0] = 0.f; cp[nt][1] = 0.f; }

    #pragma unroll
    for (int mt = 0; mt < 2; mt++) {
        const int o  = half * 128 + wo * 32 + mt * 16 + g;
        const int o2 = o + 8;
        const float bias1 = __ldg(&b2[o]);
        const float bias2 = __ldg(&b2[o2]);
        const float wc1 = __ldg(&w_col[o * NN + hloc]);
        const float wc2 = __ldg(&w_col[o2 * NN + hloc]);
        #pragma unroll
        for (int nt = 0; nt < 4; nt++) {
            const int p  = wp * 32 + nt * 8 + 2 * tig;
            const int w0 = p & 63;
            float2 wrA = __ldg(reinterpret_cast<const float2*>(&w_row[o * NN + w0]));
            float2 wrB = __ldg(reinterpret_cast<const float2*>(&w_row[o2 * NN + w0]));
            float r0 = fmaxf(acc[mt][nt][0] + bias1, 0.f);
            float r1 = fmaxf(acc[mt][nt][1] + bias1, 0.f);
            float r2 = fmaxf(acc[mt][nt][2] + bias2, 0.f);
            float r3 = fmaxf(acc[mt][nt][3] + bias2, 0.f);
            rowp += r0 * wrA.x + r1 * wrA.y + r2 * wrB.x + r3 * wrB.y;
            cp[nt][0] += r0 * wc1 + r2 * wc2;
            cp[nt][1] += r1 * wc1 + r3 * wc2;
        }
    }

    #pragma unroll
    for (int m = 16; m >= 1; m >>= 1)
        rowp += __shfl_xor_sync(0xffffffffu, rowp, m);
    if (lane == 0) atomicAdd(&rowred[hrow], rowp);

    #pragma unroll
    for (int nt = 0; nt < 4; nt++) {
        #pragma unroll
        for (int q = 0; q < 2; q++) {
            cp[nt][q] += __shfl_xor_sync(0xffffffffu, cp[nt][q], 4);
            cp[nt][q] += __shfl_xor_sync(0xffffffffu, cp[nt][q], 8);
            cp[nt][q] += __shfl_xor_sync(0xffffffffu, cp[nt][q], 16);
        }
    }
    if (g == 0) {
        #pragma unroll
        for (int nt = 0; nt < 4; nt++) {
            int p = wp * 32 + nt * 8 + 2 * tig;
            atomicAdd(&colred[p & 63], cp[nt][0]);
            atomicAdd(&colred[(p + 1) & 63], cp[nt][1]);
        }
    }
    __syncthreads();

    if (tid < 2)
        g_rowpart[half * (BB * NN) + t * 2 + tid] = rowred[tid];
    if (tid < 64)
        g_cp[((size_t)half * 1024 + t) * NN + tid] = colred[tid];
}

// =====================================================================
// Kernel 3: combine partials into final scores
// =====================================================================
__global__ void combine_kernel(const float* __restrict__ b_row,
                               const float* __restrict__ b_col)
{
    int b = blockIdx.x;
    int w = threadIdx.x;
    float s = __ldg(&b_col[0]);
    #pragma unroll 4
    for (int tt = 0; tt < 32; tt++) {
        s += g_cp[(size_t)(b * 32 + tt) * NN + w];
        s += g_cp[(size_t)(1024 + b * 32 + tt) * NN + w];
    }
    g_colscore[b * NN + w] = s;
    int bh = b * NN + w;
    g_rowscore[bh] = g_rowpart[bh] + g_rowpart[BB * NN + bh] + __ldg(&b_row[0]);
}

// =====================================================================
// Kernel 4: differentiable bitonic sort -> permutation matrix P
// =====================================================================
#define PPAD 65
__global__ void __launch_bounds__(256) sort_kernel()
{
    __shared__ float P[NN * PPAD];
    __shared__ float xsh[NN];
    __shared__ float alph[32];
    __shared__ int   pa[32], pb[32];

    const int tid  = threadIdx.x;
    const int s    = blockIdx.x;
    const int kind = s >> 5;
    const int b    = s & 31;
    const float* sc = kind ? g_colscore : g_rowscore;

    if (tid < NN) xsh[tid] = sc[b * NN + tid];
    for (int idx = tid; idx < NN * NN; idx += 256) {
        int r = idx >> 6, c = idx & 63;
        P[r * PPAD + c] = (r == c) ? 1.f : 0.f;
    }
    __syncthreads();

    for (int blk = 0; blk < 6; blk++) {
        for (int lay = 0; lay <= blk; lay++) {
            int m = 1 << (blk - lay);
            if (tid < 32) {
                int q  = tid;
                int ix = ((q & ~(m - 1)) << 1) | (q & (m - 1));
                int a = ix, bidx = ix + m;
                if ((ix >> (blk + 1)) & 1) { int tswap = a; a = bidx; bidx = tswap; }
                pa[q] = a; pb[q] = bidx;
                float xa = xsh[a], xb = xsh[bidx];
                float al = atanf((xb - xa) * 50.f) * 0.31830988618379067f + 0.5f;
                alph[q] = al;
                xsh[a]    = al * xa + (1.f - al) * xb;
                xsh[bidx] = (1.f - al) * xa + al * xb;
            }
            __syncthreads();
            #pragma unroll
            for (int it = 0; it < 8; it++) {
                int idx = tid + it * 256;
                int r = idx >> 5, q = idx & 31;
                int a = pa[q], bidx = pb[q];
                float al = alph[q];
                float Pa = P[r * PPAD + a], Pb = P[r * PPAD + bidx];
                P[r * PPAD + a]    = al * Pa + (1.f - al) * Pb;
                P[r * PPAD + bidx] = (1.f - al) * Pa + al * Pb;
            }
            __syncthreads();
        }
    }

    for (int idx = tid; idx < NN * NN; idx += 256)
        g_P[(size_t)(kind * BB + b) * NN * NN + idx] = P[(idx >> 6) * PPAD + (idx & 63)];
}

// =====================================================================
// Kernel 5: out[b,c] = P_col * (P_row * X)^T     (one block per (b,c))
// Xs/Yt union -> 50.7KB smem -> 4 blocks/SM (was 3).
// =====================================================================
#define YPAD 68
struct ApplySmem {
    union {
        float Xs[NN * NN];      // phase 1 input (dead after phase 1)
        float Yt[NN * YPAD];    // phase 2 input
    } u;
    float Prs[NN * PPAD];
    float Pcs[NN * PPAD];
};

__global__ void __launch_bounds__(128) apply_kernel(
    const float* __restrict__ x, float* __restrict__ out)
{
    extern __shared__ unsigned char dyn_smem[];
    ApplySmem* sm = reinterpret_cast<ApplySmem*>(dyn_smem);

    const int tid = threadIdx.x;
    const int bc  = blockIdx.x;
    const int b   = bc >> 7;

    {
        const float4* xg = reinterpret_cast<const float4*>(x) + (size_t)bc * (NN * NN / 4);
        float4* Xs4 = reinterpret_cast<float4*>(sm->u.Xs);
        #pragma unroll
        for (int j = 0; j < 8; j++) Xs4[tid + j * 128] = xg[tid + j * 128];
    }
    {
        const float4* pr4 = reinterpret_cast<const float4*>(&g_P[(size_t)b * NN * NN]);
        const float4* pc4 = reinterpret_cast<const float4*>(&g_P[(size_t)(BB + b) * NN * NN]);
        #pragma unroll
        for (int j = 0; j < 8; j++) {
            int idx = tid + j * 128;
            int l = idx * 4, r = l >> 6, c = l & 63;
            float4 v = pr4[idx];
            float* d = &sm->Prs[r * PPAD + c];
            d[0] = v.x; d[1] = v.y; d[2] = v.z; d[3] = v.w;
            float4 u = pc4[idx];
            float* e = &sm->Pcs[r * PPAD + c];
            e[0] = u.x; e[1] = u.y; e[2] = u.z; e[3] = u.w;
        }
    }
    __syncthreads();

    const int ig = tid >> 4, kg = tid & 15;
    const int i0 = ig * 8,   k0 = kg * 4;

    // phase 1: Y[i][k] = sum_j Prs[i][j] * X[j][k]
    ULL acc[8][2];
    #pragma unroll
    for (int ii = 0; ii < 8; ii++) { acc[ii][0] = 0ull; acc[ii][1] = 0ull; }

    #pragma unroll 4
    for (int j = 0; j < NN; j++) {
        const ULL* xp = reinterpret_cast<const ULL*>(&sm->u.Xs[j * NN + k0]);
        ULL xv0 = xp[0], xv1 = xp[1];
        #pragma unroll
        for (int ii = 0; ii < 8; ii++) {
            float p = sm->Prs[(i0 + ii) * PPAD + j];
            ULL pp = pack2(p, p);
            acc[ii][0] = fma2(xv0, pp, acc[ii][0]);
            acc[ii][1] = fma2(xv1, pp, acc[ii][1]);
        }
    }
    // hold Y in registers, barrier, then overwrite Xs region with Yt
    {
        float yv[8][4];
        #pragma unroll
        for (int ii = 0; ii < 8; ii++) {
            unpack2(acc[ii][0], yv[ii][0], yv[ii][1]);
            unpack2(acc[ii][1], yv[ii][2], yv[ii][3]);
        }
        __syncthreads();   // all Xs reads complete before Yt overwrites
        #pragma unroll
        for (int kk = 0; kk < 4; kk++) {
            float4 v0 = make_float4(yv[0][kk], yv[1][kk], yv[2][kk], yv[3][kk]);
            float4 v1 = make_float4(yv[4][kk], yv[5][kk], yv[6][kk], yv[7][kk]);
            *reinterpret_cast<float4*>(&sm->u.Yt[(k0 + kk) * YPAD + i0])     = v0;
            *reinterpret_cast<float4*>(&sm->u.Yt[(k0 + kk) * YPAD + i0 + 4]) = v1;
        }
    }
    __syncthreads();

    // phase 2: out[i][k] = sum_j Pcs[i][j] * Yt[j][k]
    #pragma unroll
    for (int ii = 0; ii < 8; ii++) { acc[ii][0] = 0ull; acc[ii][1] = 0ull; }

    #pragma unroll 4
    for (int j = 0; j < NN; j++) {
        const ULL* yp = reinterpret_cast<const ULL*>(&sm->u.Yt[j * YPAD + k0]);
        ULL yv0 = yp[0], yv1 = yp[1];
        #pragma unroll
        for (int ii = 0; ii < 8; ii++) {
            float p = sm->Pcs[(i0 + ii) * PPAD + j];
            ULL pp = pack2(p, p);
            acc[ii][0] = fma2(yv0, pp, acc[ii][0]);
            acc[ii][1] = fma2(yv1, pp, acc[ii][1]);
        }
    }

    float* og = out + (size_t)bc * NN * NN;
    #pragma unroll
    for (int ii = 0; ii < 8; ii++) {
        float o0, o1, o2, o3;
        unpack2(acc[ii][0], o0, o1);
        unpack2(acc[ii][1], o2, o3);
        *reinterpret_cast<float4*>(&og[(ii + i0) * NN + k0]) = make_float4(o0, o1, o2, o3);
    }
}

// =====================================================================
// launcher
// =====================================================================
extern "C" void kernel_launch(void* const* d_in, const int* in_sizes, int n_in,
                              void* d_out, int out_size)
{
    const float* x     = (const float*)d_in[0];
    const float* w1    = (const float*)d_in[1];
    const float* b1    = (const float*)d_in[2];
    const float* w2    = (const float*)d_in[3];
    const float* b2    = (const float*)d_in[4];
    const float* w_row = (const float*)d_in[5];
    const float* b_row = (const float*)d_in[6];
    const float* w_col = (const float*)d_in[7];
    const float* b_col = (const float*)d_in[8];
    float* out = (float*)d_out;

    const int apply_smem = (int)sizeof(ApplySmem);
    cudaFuncSetAttribute(apply_kernel, cudaFuncAttributeMaxDynamicSharedMemorySize, apply_smem);

    prep_w2_kernel<<<HID * HID / 256, 256>>>(w2);
    conv1_kernel<<<dim3(1024, 2), 256>>>(x, w1, b1);
    conv2_mma_kernel<<<dim3(1024, 2), 512>>>(b2, w_row, w_col);
    combine_kernel<<<BB, NN>>>(b_row, b_col);
    sort_kernel<<<2 * BB, 256>>>();
    apply_kernel<<<BB * CC, 128, apply_smem>>>(x, out);
}

// round 17
// speedup vs baseline: 1.1989x; 1.0338x over previous
#include <cuda_runtime.h>
#include <cuda_bf16.h>
#include <cstdint>

// Problem constants
#define BB   32
#define CC   128
#define NN   64
#define HID  256
#define NPX  (BB * NN * NN)        // 131072 pixels

typedef unsigned long long ULL;
typedef unsigned int uint;

// ---------- packed f32x2 helpers ----------
__device__ __forceinline__ ULL pack2(float a, float b) {
    ULL r;
    asm("mov.b64 %0, {%1, %2};" : "=l"(r) : "r"(__float_as_uint(a)), "r"(__float_as_uint(b)));
    return r;
}
__device__ __forceinline__ void unpack2(ULL v, float& a, float& b) {
    unsigned lo, hi;
    asm("mov.b64 {%0, %1}, %2;" : "=r"(lo), "=r"(hi) : "l"(v));
    a = __uint_as_float(lo); b = __uint_as_float(hi);
}
__device__ __forceinline__ ULL fma2(ULL a, ULL b, ULL c) {
    ULL d;
    asm("fma.rn.f32x2 %0, %1, %2, %3;" : "=l"(d) : "l"(a), "l"(b), "l"(c));
    return d;
}

// ---------- mma.sync m16n8k16 bf16 ----------
#define MMA16816(d, a, b) \
    asm volatile("mma.sync.aligned.m16n8k16.row.col.f32.bf16.bf16.f32 " \
                 "{%0,%1,%2,%3}, {%4,%5,%6,%7}, {%8,%9}, {%0,%1,%2,%3};" \
                 : "+f"((d)[0]), "+f"((d)[1]), "+f"((d)[2]), "+f"((d)[3]) \
                 : "r"((a)[0]), "r"((a)[1]), "r"((a)[2]), "r"((a)[3]), \
                   "r"((b)[0]), "r"((b)[1]))

// ---------- cp.async ----------
__device__ __forceinline__ uint smem_u32(const void* p) {
    return (uint)__cvta_generic_to_shared(p);
}
#define CP_ASYNC16(dst, src) \
    asm volatile("cp.async.cg.shared.global [%0], [%1], 16;" :: "r"(dst), "l"(src))
#define CP_COMMIT() asm volatile("cp.async.commit_group;" ::: "memory")
#define CP_WAIT0()  asm volatile("cp.async.wait_group 0;" ::: "memory")

// ---------- device scratch (no allocations allowed) ----------
__device__ __nv_bfloat16 g_xhi[(size_t)NPX * CC];     // 32 MB  x hi split, [px][c]
__device__ __nv_bfloat16 g_xlo[(size_t)NPX * CC];     // 32 MB  x lo split
__device__ __nv_bfloat16 g_w1hi[HID * CC];
__device__ __nv_bfloat16 g_w1lo[HID * CC];
__device__ __nv_bfloat16 g_hhi[(size_t)NPX * HID];    // 67 MB  h1 hi split, [px][k]
__device__ __nv_bfloat16 g_hlo[(size_t)NPX * HID];    // 67 MB  h1 lo split
__device__ __nv_bfloat16 g_w2hi[HID * HID];
__device__ __nv_bfloat16 g_w2lo[HID * HID];
__device__ float g_rowpart[2 * BB * NN];
__device__ float g_cp[2 * 1024 * NN];
__device__ float g_rowscore[BB * NN];
__device__ float g_colscore[BB * NN];
__device__ float g_P[2 * BB * NN * NN];

// =====================================================================
// Kernel 0a: split w1 + w2 into bf16 hi/lo
// =====================================================================
__global__ void prep_w_kernel(const float* __restrict__ w1,
                              const float* __restrict__ w2)
{
    int i = blockIdx.x * 256 + threadIdx.x;   // grid covers 98304
    if (i < HID * CC) {
        float f = w1[i];
        __nv_bfloat16 h = __float2bfloat16(f);
        g_w1hi[i] = h;
        g_w1lo[i] = __float2bfloat16(f - __bfloat162float(h));
    } else if (i < HID * CC + HID * HID) {
        int j = i - HID * CC;
        float f = w2[j];
        __nv_bfloat16 h = __float2bfloat16(f);
        g_w2hi[j] = h;
        g_w2lo[j] = __float2bfloat16(f - __bfloat162float(h));
    }
}

// =====================================================================
// Kernel 0b: transpose x -> bf16 hi/lo [px][c]
// 2048 blocks x 256 thr; each block: 64 px, all 128 c.
// =====================================================================
__global__ void __launch_bounds__(256) prep_x_kernel(const float* __restrict__ x)
{
    __shared__ float tile[128][65];

    const int tid = threadIdx.x;
    const size_t pxg0 = (size_t)blockIdx.x * 64;
    const int b = (int)(pxg0 >> 12);
    const int inner0 = (int)(pxg0 & 4095);
    const float* xb = x + ((size_t)b * CC) * 4096 + inner0;

    #pragma unroll
    for (int j = 0; j < 32; j++) {
        int idx = tid + j * 256;      // 8192 = 128c x 64px
        int c = idx >> 6, p = idx & 63;
        tile[c][p] = xb[(size_t)c * 4096 + p];
    }
    __syncthreads();

    #pragma unroll
    for (int j = 0; j < 4; j++) {
        int idx = tid + j * 256;      // 1024 = 64px x 16 segs
        int p = idx >> 4, seg = idx & 15;
        uint hi[4], lo[4];
        #pragma unroll
        for (int q = 0; q < 4; q++) {
            float f0 = tile[seg * 8 + q * 2][p];
            float f1 = tile[seg * 8 + q * 2 + 1][p];
            __nv_bfloat16 h0 = __float2bfloat16(f0);
            __nv_bfloat16 h1 = __float2bfloat16(f1);
            __nv_bfloat162 hp; hp.x = h0; hp.y = h1;
            hi[q] = *reinterpret_cast<uint*>(&hp);
            __nv_bfloat162 lp;
            lp.x = __float2bfloat16(f0 - __bfloat162float(h0));
            lp.y = __float2bfloat16(f1 - __bfloat162float(h1));
            lo[q] = *reinterpret_cast<uint*>(&lp);
        }
        size_t off = (pxg0 + p) * CC + seg * 8;
        *reinterpret_cast<uint4*>(&g_xhi[off]) = make_uint4(hi[0], hi[1], hi[2], hi[3]);
        *reinterpret_cast<uint4*>(&g_xlo[off]) = make_uint4(lo[0], lo[1], lo[2], lo[3]);
    }
}

// =====================================================================
// Kernel 1: conv1 via mma.sync bf16 x3 splits + relu -> h1 hi/lo [px][k].
// Same skeleton as conv2_mma; K=128 (4 chunks). Epilogue does an smem
// transpose (reusing the staging buffers) for coalesced [px][HID] stores.
// =====================================================================
#define KC2  32
#define KCP  40      // 80B row stride: 16B-aligned staging, conflict-free LDS
#define TP   136     // transpose row pad: 272B, 16B-aligned

__global__ void __launch_bounds__(512, 1) conv1_mma_kernel(
    const float* __restrict__ b1)
{
    __shared__ __align__(16) char sraw[81920];
    __nv_bfloat16* xs_hi = reinterpret_cast<__nv_bfloat16*>(sraw);           // [2][128][KCP]
    __nv_bfloat16* xs_lo = reinterpret_cast<__nv_bfloat16*>(sraw + 20480);
    __nv_bfloat16* ws_hi = reinterpret_cast<__nv_bfloat16*>(sraw + 40960);
    __nv_bfloat16* ws_lo = reinterpret_cast<__nv_bfloat16*>(sraw + 61440);

    const int tid  = threadIdx.x;
    const int t    = blockIdx.x;
    const int half = blockIdx.y;
    const int warp = tid >> 5;
    const int lane = tid & 31;
    const int g    = lane >> 2;
    const int tig  = lane & 3;
    const int wo   = warp >> 2;
    const int wp   = warp & 3;

    const size_t pxbase = (size_t)t * 128;

    float acc[2][4][4];
    #pragma unroll
    for (int mt = 0; mt < 2; mt++)
        #pragma unroll
        for (int nt = 0; nt < 4; nt++)
            #pragma unroll
            for (int i = 0; i < 4; i++) acc[mt][nt][i] = 0.f;

    const int srow = tid >> 2;
    const int sseg = tid & 3;
    const size_t xoff_base = (pxbase + srow) * CC + sseg * 8;
    const size_t woff_base = (size_t)(half * 128 + srow) * CC + sseg * 8;

    #define SIDX(buf, r, c) ((((buf) * 128 + (r)) * KCP + (c)))

    // prologue: chunk 0 -> buffer 0
    CP_ASYNC16(smem_u32(&xs_hi[SIDX(0, srow, sseg * 8)]), &g_xhi[xoff_base]);
    CP_ASYNC16(smem_u32(&xs_lo[SIDX(0, srow, sseg * 8)]), &g_xlo[xoff_base]);
    CP_ASYNC16(smem_u32(&ws_hi[SIDX(0, srow, sseg * 8)]), &g_w1hi[woff_base]);
    CP_ASYNC16(smem_u32(&ws_lo[SIDX(0, srow, sseg * 8)]), &g_w1lo[woff_base]);
    CP_COMMIT();

    const int NCHUNK = CC / KC2;   // 4
    for (int kc = 0; kc < NCHUNK; kc++) {
        CP_WAIT0();
        __syncthreads();

        if (kc + 1 < NCHUNK) {
            const int nb = (kc + 1) & 1;
            const size_t koff = (size_t)(kc + 1) * KC2;
            CP_ASYNC16(smem_u32(&xs_hi[SIDX(nb, srow, sseg * 8)]), &g_xhi[xoff_base + koff]);
            CP_ASYNC16(smem_u32(&xs_lo[SIDX(nb, srow, sseg * 8)]), &g_xlo[xoff_base + koff]);
            CP_ASYNC16(smem_u32(&ws_hi[SIDX(nb, srow, sseg * 8)]), &g_w1hi[woff_base + koff]);
            CP_ASYNC16(smem_u32(&ws_lo[SIDX(nb, srow, sseg * 8)]), &g_w1lo[woff_base + koff]);
            CP_COMMIT();
        }

        const int buf = kc & 1;
        #pragma unroll
        for (int kk = 0; kk < 2; kk++) {
            const int kb = kk * 16;
            uint a[2][4], bh[4][2], bl[4][2];
            #pragma unroll
            for (int nt = 0; nt < 4; nt++) {
                int rp = wp * 32 + nt * 8 + g;
                bh[nt][0] = *reinterpret_cast<const uint*>(&xs_hi[SIDX(buf, rp, kb + 2 * tig)]);
                bh[nt][1] = *reinterpret_cast<const uint*>(&xs_hi[SIDX(buf, rp, kb + 2 * tig + 8)]);
                bl[nt][0] = *reinterpret_cast<const uint*>(&xs_lo[SIDX(buf, rp, kb + 2 * tig)]);
                bl[nt][1] = *reinterpret_cast<const uint*>(&xs_lo[SIDX(buf, rp, kb + 2 * tig + 8)]);
            }
            #pragma unroll
            for (int mt = 0; mt < 2; mt++) {
                int ro = wo * 32 + mt * 16 + g;
                a[mt][0] = *reinterpret_cast<const uint*>(&ws_hi[SIDX(buf, ro, kb + 2 * tig)]);
                a[mt][1] = *reinterpret_cast<const uint*>(&ws_hi[SIDX(buf, ro + 8, kb + 2 * tig)]);
                a[mt][2] = *reinterpret_cast<const uint*>(&ws_hi[SIDX(buf, ro, kb + 2 * tig + 8)]);
                a[mt][3] = *reinterpret_cast<const uint*>(&ws_hi[SIDX(buf, ro + 8, kb + 2 * tig + 8)]);
            }
            #pragma unroll
            for (int mt = 0; mt < 2; mt++)
                #pragma unroll
                for (int nt = 0; nt < 4; nt++) {
                    MMA16816(acc[mt][nt], a[mt], bh[nt]);
                    MMA16816(acc[mt][nt], a[mt], bl[nt]);
                }
            #pragma unroll
            for (int mt = 0; mt < 2; mt++) {
                int ro = wo * 32 + mt * 16 + g;
                a[mt][0] = *reinterpret_cast<const uint*>(&ws_lo[SIDX(buf, ro, kb + 2 * tig)]);
                a[mt][1] = *reinterpret_cast<const uint*>(&ws_lo[SIDX(buf, ro + 8, kb + 2 * tig)]);
                a[mt][2] = *reinterpret_cast<const uint*>(&ws_lo[SIDX(buf, ro, kb + 2 * tig + 8)]);
                a[mt][3] = *reinterpret_cast<const uint*>(&ws_lo[SIDX(buf, ro + 8, kb + 2 * tig + 8)]);
            }
            #pragma unroll
            for (int mt = 0; mt < 2; mt++)
                #pragma unroll
                for (int nt = 0; nt < 4; nt++)
                    MMA16816(acc[mt][nt], a[mt], bh[nt]);
        }
    }
    __syncthreads();    // all fragment reads done; staging smem reusable

    // ---- epilogue: bias + relu + split, smem transpose, coalesced store ----
    __nv_bfloat16* thi = reinterpret_cast<__nv_bfloat16*>(sraw);            // [128][TP]
    __nv_bfloat16* tlo = reinterpret_cast<__nv_bfloat16*>(sraw + 34816);

    #pragma unroll
    for (int mt = 0; mt < 2; mt++) {
        const int r0 = wo * 32 + mt * 16 + g;
        const int r1 = r0 + 8;
        const float bias0 = __ldg(&b1[half * 128 + r0]);
        const float bias1 = __ldg(&b1[half * 128 + r1]);
        #pragma unroll
        for (int nt = 0; nt < 4; nt++) {
            const int px0 = wp * 32 + nt * 8 + 2 * tig;
            float v0 = fmaxf(acc[mt][nt][0] + bias0, 0.f);   // (r0, px0)
            float v1 = fmaxf(acc[mt][nt][1] + bias0, 0.f);   // (r0, px0+1)
            float v2 = fmaxf(acc[mt][nt][2] + bias1, 0.f);   // (r1, px0)
            float v3 = fmaxf(acc[mt][nt][3] + bias1, 0.f);   // (r1, px0+1)
            __nv_bfloat16 h0 = __float2bfloat16(v0);
            __nv_bfloat16 h1 = __float2bfloat16(v1);
            __nv_bfloat16 h2 = __float2bfloat16(v2);
            __nv_bfloat16 h3 = __float2bfloat16(v3);
            thi[px0 * TP + r0]       = h0;
            thi[(px0 + 1) * TP + r0] = h1;
            thi[px0 * TP + r1]       = h2;
            thi[(px0 + 1) * TP + r1] = h3;
            tlo[px0 * TP + r0]       = __float2bfloat16(v0 - __bfloat162float(h0));
            tlo[(px0 + 1) * TP + r0] = __float2bfloat16(v1 - __bfloat162float(h1));
            tlo[px0 * TP + r1]       = __float2bfloat16(v2 - __bfloat162float(h2));
            tlo[(px0 + 1) * TP + r1] = __float2bfloat16(v3 - __bfloat162float(h3));
        }
    }
    __syncthreads();

    #pragma unroll
    for (int j = 0; j < 4; j++) {
        int idx = tid + j * 512;     // 2048 = 128px x 16 segs
        int p = idx >> 4, seg = idx & 15;
        size_t off = (pxbase + p) * HID + half * 128 + seg * 8;
        *reinterpret_cast<uint4*>(&g_hhi[off]) =
            *reinterpret_cast<const uint4*>(&thi[p * TP + seg * 8]);
        *reinterpret_cast<uint4*>(&g_hlo[off]) =
            *reinterpret_cast<const uint4*>(&tlo[p * TP + seg * 8]);
    }
    #undef SIDX
}

// =====================================================================
// Kernel 2: conv2 via mma.sync bf16 x3 splits + relu + score partials.
// (round-16 version, unchanged)
// =====================================================================
__global__ void __launch_bounds__(512, 1) conv2_mma_kernel(
    const float* __restrict__ b2,
    const float* __restrict__ w_row, const float* __restrict__ w_col)
{
    __shared__ __align__(16) __nv_bfloat16 hs_hi[2][128][KCP];
    __shared__ __align__(16) __nv_bfloat16 hs_lo[2][128][KCP];
    __shared__ __align__(16) __nv_bfloat16 ws_hi[2][128][KCP];
    __shared__ __align__(16) __nv_bfloat16 ws_lo[2][128][KCP];
    __shared__ float colred[64];
    __shared__ float rowred[2];

    const int tid  = threadIdx.x;
    const int t    = blockIdx.x;
    const int half = blockIdx.y;
    const int warp = tid >> 5;
    const int lane = tid & 31;
    const int g    = lane >> 2;
    const int tig  = lane & 3;
    const int wo   = warp >> 2;
    const int wp   = warp & 3;

    if (tid < 64) colred[tid] = 0.f;
    if (tid < 2)  rowred[tid] = 0.f;

    const size_t pxbase = (size_t)t * 128;

    float acc[2][4][4];
    #pragma unroll
    for (int mt = 0; mt < 2; mt++)
        #pragma unroll
        for (int nt = 0; nt < 4; nt++)
            #pragma unroll
            for (int i = 0; i < 4; i++) acc[mt][nt][i] = 0.f;

    const int srow = tid >> 2;
    const int sseg = tid & 3;
    const size_t hoff_base = (pxbase + srow) * HID + sseg * 8;
    const size_t woff_base = (size_t)(half * 128 + srow) * HID + sseg * 8;

    CP_ASYNC16(smem_u32(&hs_hi[0][srow][sseg * 8]), &g_hhi[hoff_base]);
    CP_ASYNC16(smem_u32(&hs_lo[0][srow][sseg * 8]), &g_hlo[hoff_base]);
    CP_ASYNC16(smem_u32(&ws_hi[0][srow][sseg * 8]), &g_w2hi[woff_base]);
    CP_ASYNC16(smem_u32(&ws_lo[0][srow][sseg * 8]), &g_w2lo[woff_base]);
    CP_COMMIT();

    const int NCHUNK = HID / KC2;    // 8
    for (int kc = 0; kc < NCHUNK; kc++) {
        CP_WAIT0();
        __syncthreads();

        if (kc + 1 < NCHUNK) {
            const int nb = (kc + 1) & 1;
            const size_t koff = (size_t)(kc + 1) * KC2;
            CP_ASYNC16(smem_u32(&hs_hi[nb][srow][sseg * 8]), &g_hhi[hoff_base + koff]);
            CP_ASYNC16(smem_u32(&hs_lo[nb][srow][sseg * 8]), &g_hlo[hoff_base + koff]);
            CP_ASYNC16(smem_u32(&ws_hi[nb][srow][sseg * 8]), &g_w2hi[woff_base + koff]);
            CP_ASYNC16(smem_u32(&ws_lo[nb][srow][sseg * 8]), &g_w2lo[woff_base + koff]);
            CP_COMMIT();
        }

        const int buf = kc & 1;
        #pragma unroll
        for (int kk = 0; kk < 2; kk++) {
            const int kb = kk * 16;
            uint a[2][4], bh[4][2], bl[4][2];
            #pragma unroll
            for (int nt = 0; nt < 4; nt++) {
                int rp = wp * 32 + nt * 8 + g;
                bh[nt][0] = *reinterpret_cast<const uint*>(&hs_hi[buf][rp][kb + 2 * tig]);
                bh[nt][1] = *reinterpret_cast<const uint*>(&hs_hi[buf][rp][kb + 2 * tig + 8]);
                bl[nt][0] = *reinterpret_cast<const uint*>(&hs_lo[buf][rp][kb + 2 * tig]);
                bl[nt][1] = *reinterpret_cast<const uint*>(&hs_lo[buf][rp][kb + 2 * tig + 8]);
            }
            #pragma unroll
            for (int mt = 0; mt < 2; mt++) {
                int ro = wo * 32 + mt * 16 + g;
                a[mt][0] = *reinterpret_cast<const uint*>(&ws_hi[buf][ro][kb + 2 * tig]);
                a[mt][1] = *reinterpret_cast<const uint*>(&ws_hi[buf][ro + 8][kb + 2 * tig]);
                a[mt][2] = *reinterpret_cast<const uint*>(&ws_hi[buf][ro][kb + 2 * tig + 8]);
                a[mt][3] = *reinterpret_cast<const uint*>(&ws_hi[buf][ro + 8][kb + 2 * tig + 8]);
            }
            #pragma unroll
            for (int mt = 0; mt < 2; mt++)
                #pragma unroll
                for (int nt = 0; nt < 4; nt++) {
                    MMA16816(acc[mt][nt], a[mt], bh[nt]);
                    MMA16816(acc[mt][nt], a[mt], bl[nt]);
                }
            #pragma unroll
            for (int mt = 0; mt < 2; mt++) {
                int ro = wo * 32 + mt * 16 + g;
                a[mt][0] = *reinterpret_cast<const uint*>(&ws_lo[buf][ro][kb + 2 * tig]);
                a[mt][1] = *reinterpret_cast<const uint*>(&ws_lo[buf][ro + 8][kb + 2 * tig]);
                a[mt][2] = *reinterpret_cast<const uint*>(&ws_lo[buf][ro][kb + 2 * tig + 8]);
                a[mt][3] = *reinterpret_cast<const uint*>(&ws_lo[buf][ro + 8][kb + 2 * tig + 8]);
            }
            #pragma unroll
            for (int mt = 0; mt < 2; mt++)
                #pragma unroll
                for (int nt = 0; nt < 4; nt++)
                    MMA16816(acc[mt][nt], a[mt], bh[nt]);
        }
    }

    // ---- epilogue: bias + relu + score partials ----
    const int hrow = (wp >= 2) ? 1 : 0;
    const int bh_idx = t * 2 + hrow;
    const int hloc = bh_idx & 63;

    float rowp = 0.f;
    float cp[4][2];
    #pragma unroll
    for (int nt = 0; nt < 4; nt++) { cp[nt][0] = 0.f; cp[nt][1] = 0.f; }

    #pragma unroll
    for (int mt = 0; mt < 2; mt++) {
        const int o  = half * 128 + wo * 32 + mt * 16 + g;
        const int o2 = o + 8;
        const float bias1 = __ldg(&b2[o]);
        const float bias2 = __ldg(&b2[o2]);
        const float wc1 = __ldg(&w_col[o * NN + hloc]);
        const float wc2 = __ldg(&w_col[o2 * NN + hloc]);
        #pragma unroll
        for (int nt = 0; nt < 4; nt++) {
            const int p  = wp * 32 + nt * 8 + 2 * tig;
            const int w0 = p & 63;
            float2 wrA = __ldg(reinterpret_cast<const float2*>(&w_row[o * NN + w0]));
            float2 wrB = __ldg(reinterpret_cast<const float2*>(&w_row[o2 * NN + w0]));
            float r0 = fmaxf(acc[mt][nt][0] + bias1, 0.f);
            float r1 = fmaxf(acc[mt][nt][1] + bias1, 0.f);
            float r2 = fmaxf(acc[mt][nt][2] + bias2, 0.f);
            float r3 = fmaxf(acc[mt][nt][3] + bias2, 0.f);
            rowp += r0 * wrA.x + r1 * wrA.y + r2 * wrB.x + r3 * wrB.y;
            cp[nt][0] += r0 * wc1 + r2 * wc2;
            cp[nt][1] += r1 * wc1 + r3 * wc2;
        }
    }

    #pragma unroll
    for (int m = 16; m >= 1; m >>= 1)
        rowp += __shfl_xor_sync(0xffffffffu, rowp, m);
    if (lane == 0) atomicAdd(&rowred[hrow], rowp);

    #pragma unroll
    for (int nt = 0; nt < 4; nt++) {
        #pragma unroll
        for (int q = 0; q < 2; q++) {
            cp[nt][q] += __shfl_xor_sync(0xffffffffu, cp[nt][q], 4);
            cp[nt][q] += __shfl_xor_sync(0xffffffffu, cp[nt][q], 8);
            cp[nt][q] += __shfl_xor_sync(0xffffffffu, cp[nt][q], 16);
        }
    }
    if (g == 0) {
        #pragma unroll
        for (int nt = 0; nt < 4; nt++) {
            int p = wp * 32 + nt * 8 + 2 * tig;
            atomicAdd(&colred[p & 63], cp[nt][0]);
            atomicAdd(&colred[(p + 1) & 63], cp[nt][1]);
        }
    }
    __syncthreads();

    if (tid < 2)
        g_rowpart[half * (BB * NN) + t * 2 + tid] = rowred[tid];
    if (tid < 64)
        g_cp[((size_t)half * 1024 + t) * NN + tid] = colred[tid];
}

// =====================================================================
// Kernel 3: combine partials into final scores
// =====================================================================
__global__ void combine_kernel(const float* __restrict__ b_row,
                               const float* __restrict__ b_col)
{
    int b = blockIdx.x;
    int w = threadIdx.x;
    float s = __ldg(&b_col[0]);
    #pragma unroll 4
    for (int tt = 0; tt < 32; tt++) {
        s += g_cp[(size_t)(b * 32 + tt) * NN + w];
        s += g_cp[(size_t)(1024 + b * 32 + tt) * NN + w];
    }
    g_colscore[b * NN + w] = s;
    int bh = b * NN + w;
    g_rowscore[bh] = g_rowpart[bh] + g_rowpart[BB * NN + bh] + __ldg(&b_row[0]);
}

// =====================================================================
// Kernel 4: differentiable bitonic sort -> permutation matrix P
// =====================================================================
#define PPAD 65
__global__ void __launch_bounds__(256) sort_kernel()
{
    __shared__ float P[NN * PPAD];
    __shared__ float xsh[NN];
    __shared__ float alph[32];
    __shared__ int   pa[32], pb[32];

    const int tid  = threadIdx.x;
    const int s    = blockIdx.x;
    const int kind = s >> 5;
    const int b    = s & 31;
    const float* sc = kind ? g_colscore : g_rowscore;

    if (tid < NN) xsh[tid] = sc[b * NN + tid];
    for (int idx = tid; idx < NN * NN; idx += 256) {
        int r = idx >> 6, c = idx & 63;
        P[r * PPAD + c] = (r == c) ? 1.f : 0.f;
    }
    __syncthreads();

    for (int blk = 0; blk < 6; blk++) {
        for (int lay = 0; lay <= blk; lay++) {
            int m = 1 << (blk - lay);
            if (tid < 32) {
                int q  = tid;
                int ix = ((q & ~(m - 1)) << 1) | (q & (m - 1));
                int a = ix, bidx = ix + m;
                if ((ix >> (blk + 1)) & 1) { int tswap = a; a = bidx; bidx = tswap; }
                pa[q] = a; pb[q] = bidx;
                float xa = xsh[a], xb = xsh[bidx];
                float al = atanf((xb - xa) * 50.f) * 0.31830988618379067f + 0.5f;
                alph[q] = al;
                xsh[a]    = al * xa + (1.f - al) * xb;
                xsh[bidx] = (1.f - al) * xa + al * xb;
            }
            __syncthreads();
            #pragma unroll
            for (int it = 0; it < 8; it++) {
                int idx = tid + it * 256;
                int r = idx >> 5, q = idx & 31;
                int a = pa[q], bidx = pb[q];
                float al = alph[q];
                float Pa = P[r * PPAD + a], Pb = P[r * PPAD + bidx];
                P[r * PPAD + a]    = al * Pa + (1.f - al) * Pb;
                P[r * PPAD + bidx] = (1.f - al) * Pa + al * Pb;
            }
            __syncthreads();
        }
    }

    for (int idx = tid; idx < NN * NN; idx += 256)
        g_P[(size_t)(kind * BB + b) * NN * NN + idx] = P[(idx >> 6) * PPAD + (idx & 63)];
}

// =====================================================================
// Kernel 5: out[b,c] = P_col * (P_row * X)^T     (one block per (b,c))
// Xs/Yt union -> 4 blocks/SM (round-16 version, unchanged)
// =====================================================================
#define YPAD 68
struct ApplySmem {
    union {
        float Xs[NN * NN];
        float Yt[NN * YPAD];
    } u;
    float Prs[NN * PPAD];
    float Pcs[NN * PPAD];
};

__global__ void __launch_bounds__(128) apply_kernel(
    const float* __restrict__ x, float* __restrict__ out)
{
    extern __shared__ unsigned char dyn_smem[];
    ApplySmem* sm = reinterpret_cast<ApplySmem*>(dyn_smem);

    const int tid = threadIdx.x;
    const int bc  = blockIdx.x;
    const int b   = bc >> 7;

    {
        const float4* xg = reinterpret_cast<const float4*>(x) + (size_t)bc * (NN * NN / 4);
        float4* Xs4 = reinterpret_cast<float4*>(sm->u.Xs);
        #pragma unroll
        for (int j = 0; j < 8; j++) Xs4[tid + j * 128] = xg[tid + j * 128];
    }
    {
        const float4* pr4 = reinterpret_cast<const float4*>(&g_P[(size_t)b * NN * NN]);
        const float4* pc4 = reinterpret_cast<const float4*>(&g_P[(size_t)(BB + b) * NN * NN]);
        #pragma unroll
        for (int j = 0; j < 8; j++) {
            int idx = tid + j * 128;
            int l = idx * 4, r = l >> 6, c = l & 63;
            float4 v = pr4[idx];
            float* d = &sm->Prs[r * PPAD + c];
            d[0] = v.x; d[1] = v.y; d[2] = v.z; d[3] = v.w;
            float4 u = pc4[idx];
            float* e = &sm->Pcs[r * PPAD + c];
            e[0] = u.x; e[1] = u.y; e[2] = u.z; e[3] = u.w;
        }
    }
    __syncthreads();

    const int ig = tid >> 4, kg = tid & 15;
    const int i0 = ig * 8,   k0 = kg * 4;

    ULL acc[8][2];
    #pragma unroll
    for (int ii = 0; ii < 8; ii++) { acc[ii][0] = 0ull; acc[ii][1] = 0ull; }

    #pragma unroll 4
    for (int j = 0; j < NN; j++) {
        const ULL* xp = reinterpret_cast<const ULL*>(&sm->u.Xs[j * NN + k0]);
        ULL xv0 = xp[0], xv1 = xp[1];
        #pragma unroll
        for (int ii = 0; ii < 8; ii++) {
            float p = sm->Prs[(i0 + ii) * PPAD + j];
            ULL pp = pack2(p, p);
            acc[ii][0] = fma2(xv0, pp, acc[ii][0]);
            acc[ii][1] = fma2(xv1, pp, acc[ii][1]);
        }
    }
    {
        float yv[8][4];
        #pragma unroll
        for (int ii = 0; ii < 8; ii++) {
            unpack2(acc[ii][0], yv[ii][0], yv[ii][1]);
            unpack2(acc[ii][1], yv[ii][2], yv[ii][3]);
        }
        __syncthreads();
        #pragma unroll
        for (int kk = 0; kk < 4; kk++) {
            float4 v0 = make_float4(yv[0][kk], yv[1][kk], yv[2][kk], yv[3][kk]);
            float4 v1 = make_float4(yv[4][kk], yv[5][kk], yv[6][kk], yv[7][kk]);
            *reinterpret_cast<float4*>(&sm->u.Yt[(k0 + kk) * YPAD + i0])     = v0;
            *reinterpret_cast<float4*>(&sm->u.Yt[(k0 + kk) * YPAD + i0 + 4]) = v1;
        }
    }
    __syncthreads();

    #pragma unroll
    for (int ii = 0; ii < 8; ii++) { acc[ii][0] = 0ull; acc[ii][1] = 0ull; }

    #pragma unroll 4
    for (int j = 0; j < NN; j++) {
        const ULL* yp = reinterpret_cast<const ULL*>(&sm->u.Yt[j * YPAD + k0]);
        ULL yv0 = yp[0], yv1 = yp[1];
        #pragma unroll
        for (int ii = 0; ii < 8; ii++) {
            float p = sm->Pcs[(i0 + ii) * PPAD + j];
            ULL pp = pack2(p, p);
            acc[ii][0] = fma2(yv0, pp, acc[ii][0]);
            acc[ii][1] = fma2(yv1, pp, acc[ii][1]);
        }
    }

    float* og = out + (size_t)bc * NN * NN;
    #pragma unroll
    for (int ii = 0; ii < 8; ii++) {
        float o0, o1, o2, o3;
        unpack2(acc[ii][0], o0, o1);
        unpack2(acc[ii][1], o2, o3);
        *reinterpret_cast<float4*>(&og[(ii + i0) * NN + k0]) = make_float4(o0, o1, o2, o3);
    }
}

// =====================================================================
// launcher
// =====================================================================
extern "C" void kernel_launch(void* const* d_in, const int* in_sizes, int n_in,
                              void* d_out, int out_size)
{
    const float* x     = (const float*)d_in[0];
    const float* w1    = (const float*)d_in[1];
    const float* b1    = (const float*)d_in[2];
    const float* w2    = (const float*)d_in[3];
    const float* b2    = (const float*)d_in[4];
    const float* w_row = (const float*)d_in[5];
    const float* b_row = (const float*)d_in[6];
    const float* w_col = (const float*)d_in[7];
    const float* b_col = (const float*)d_in[8];
    float* out = (float*)d_out;

    const int apply_smem = (int)sizeof(ApplySmem);
    cudaFuncSetAttribute(apply_kernel, cudaFuncAttributeMaxDynamicSharedMemorySize, apply_smem);

    prep_w_kernel<<<(HID * CC + HID * HID + 255) / 256, 256>>>(w1, w2);
    prep_x_kernel<<<NPX / 64, 256>>>(x);
    conv1_mma_kernel<<<dim3(1024, 2), 512>>>(b1);
    conv2_mma_kernel<<<dim3(1024, 2), 512>>>(b2, w_row, w_col);
    combine_kernel<<<BB, NN>>>(b_row, b_col);
    sort_kernel<<<2 * BB, 256>>>();
    apply_kernel<<<BB * CC, 128, apply_smem>>>(x, out);
}